// round 6
// baseline (speedup 1.0000x reference)
#include <cuda_runtime.h>
#include <cuda_bf16.h>
#include <math.h>

// Problem constants
#define BATCH   2
#define SEQ     2048
#define DMODEL  1024
#define HEADS   16
#define DH      64
#define NROWS   (BATCH * SEQ)            // 4096
#define SCALE_QK 0.125f                  // 1/sqrt(64)

// -------- device scratch (statics are the sanctioned no-alloc path) --------
__device__ float g_Qh [BATCH * HEADS * SEQ * DH];    // [b,h,s,d]   16 MB
__device__ float g_KhT[BATCH * HEADS * DH  * SEQ];   // [b,h,d,s]   16 MB
__device__ float g_Vh [BATCH * HEADS * SEQ * DH];    // [b,h,s,d]   16 MB
__device__ float g_Att[NROWS * DMODEL];              // [b,s, h*d]  16 MB
__device__ float g_Scr[(long long)BATCH * HEADS * SEQ * SEQ]; // 512 MB scores

// ---------------------------------------------------------------------------
// Generic fp32 tiled GEMM:  C = alpha * (A @ B) + bias
//   A: M x K row-major, B: K x N row-major. BM=128, BK=8, 256 threads.
//   MODE 0: C row-major M x N (per-z offset sC)
//   MODE 1: QKV head-split natural  [b,h,s,d]
//   MODE 2: K head-split TRANSPOSED [b,h,d,s]
//   MODE 3: PV output merged-heads  [b,s, h*DH + n]  (z = b*H + h)
// ---------------------------------------------------------------------------
template<int MODE, int BN_, int TM_, int TN_>
__global__ void __launch_bounds__(256, 2)
gemm_k(const float* __restrict__ A, const float* __restrict__ Bm,
       const float* __restrict__ bias, float* __restrict__ C,
       int M, int N, int K, float alpha,
       long long sA, long long sB, long long sC)
{
    constexpr int BM = 128, BK = 8;
    constexpr int CX = BN_ / TN_;     // threads along N
    const int z = blockIdx.z;
    A  += (long long)z * sA;
    Bm += (long long)z * sB;
    if (MODE == 0) C += (long long)z * sC;

    __shared__ float As[BK][BM];
    __shared__ float Bs[BK][BN_];

    const int tid = threadIdx.x;
    const int m0 = blockIdx.y * BM;
    const int n0 = blockIdx.x * BN_;

    // A-tile loader: 128x8 = 1024 floats = 256 float4, one per thread
    const int arow = tid >> 1;
    const int acol = (tid & 1) * 4;
    // B-tile loader: 8 x BN_ floats = 2*BN_ float4
    constexpr int BROWDIV = BN_ / 4;
    const int brow = tid / BROWDIV;
    const int bcol = (tid % BROWDIV) * 4;
    const bool bactive = tid < 2 * BN_;

    const int tx = tid % CX;
    const int ty = tid / CX;

    float acc[TM_][TN_];
#pragma unroll
    for (int i = 0; i < TM_; i++)
#pragma unroll
        for (int j = 0; j < TN_; j++) acc[i][j] = 0.f;

    for (int kt = 0; kt < K; kt += BK) {
        float4 a4 = *(const float4*)&A[(long long)(m0 + arow) * K + kt + acol];
        float4 b4 = make_float4(0.f, 0.f, 0.f, 0.f);
        if (bactive && (n0 + bcol) < N)
            b4 = *(const float4*)&Bm[(long long)(kt + brow) * N + n0 + bcol];

        __syncthreads();   // previous iteration's reads done
        As[acol + 0][arow] = a4.x;
        As[acol + 1][arow] = a4.y;
        As[acol + 2][arow] = a4.z;
        As[acol + 3][arow] = a4.w;
        if (bactive) *(float4*)&Bs[brow][bcol] = b4;
        __syncthreads();

#pragma unroll
        for (int k = 0; k < BK; k++) {
            float a[TM_], b[TN_];
#pragma unroll
            for (int i = 0; i < TM_; i++) a[i] = As[k][ty * TM_ + i];
#pragma unroll
            for (int j = 0; j < TN_; j++) b[j] = Bs[k][tx * TN_ + j];
#pragma unroll
            for (int i = 0; i < TM_; i++)
#pragma unroll
                for (int j = 0; j < TN_; j++)
                    acc[i][j] += a[i] * b[j];
        }
    }

    // Epilogue
#pragma unroll
    for (int i = 0; i < TM_; i++) {
        const int m = m0 + ty * TM_ + i;
#pragma unroll
        for (int j = 0; j < TN_; j++) {
            const int n = n0 + tx * TN_ + j;
            if (n >= N) continue;
            float v = acc[i][j] * alpha;
            if (bias) v += bias[n];
            if (MODE == 0) {
                C[(long long)m * N + n] = v;
            } else if (MODE == 1) {
                // m = b*SEQ+s ; n = h*DH+d  ->  [b,h,s,d]
                int b = m >> 11, s = m & (SEQ - 1);
                int h = n >> 6,  d = n & (DH - 1);
                C[(((b * HEADS + h) * SEQ + s) << 6) + d] = v;
            } else if (MODE == 2) {
                // -> [b,h,d,s]
                int b = m >> 11, s = m & (SEQ - 1);
                int h = n >> 6,  d = n & (DH - 1);
                C[(((b * HEADS + h) * DH + d) << 11) + s] = v;
            } else { // MODE 3: z = b*H+h ; m = s ; n = d  -> [b,s,h*DH+n]
                int b = z >> 4, h = z & (HEADS - 1);
                C[((long long)(b * SEQ + m)) * DMODEL + h * DH + n] = v;
            }
        }
    }
}

// ---------------------------------------------------------------------------
// Row softmax over 2048-wide rows. One 256-thread block per row, 8 vals/thread
// kept register-resident (one global read + one global write per element).
// ---------------------------------------------------------------------------
__global__ void __launch_bounds__(256)
softmax_rows(float* __restrict__ P)
{
    float* p = P + (long long)blockIdx.x * SEQ;
    const int tid = threadIdx.x;
    const int wid = tid >> 5, lid = tid & 31;
    __shared__ float red[8];

    float v[8];
#pragma unroll
    for (int i = 0; i < 8; i++) v[i] = p[tid + i * 256];

    float mx = v[0];
#pragma unroll
    for (int i = 1; i < 8; i++) mx = fmaxf(mx, v[i]);
#pragma unroll
    for (int o = 16; o; o >>= 1) mx = fmaxf(mx, __shfl_xor_sync(0xffffffffu, mx, o));
    if (lid == 0) red[wid] = mx;
    __syncthreads();
    float rmax = red[0];
#pragma unroll
    for (int w = 1; w < 8; w++) rmax = fmaxf(rmax, red[w]);
    __syncthreads();

    float s = 0.f;
#pragma unroll
    for (int i = 0; i < 8; i++) { v[i] = expf(v[i] - rmax); s += v[i]; }
#pragma unroll
    for (int o = 16; o; o >>= 1) s += __shfl_xor_sync(0xffffffffu, s, o);
    if (lid == 0) red[wid] = s;
    __syncthreads();
    float tot = 0.f;
#pragma unroll
    for (int w = 0; w < 8; w++) tot += red[w];
    const float inv = 1.f / tot;

#pragma unroll
    for (int i = 0; i < 8; i++) p[tid + i * 256] = v[i] * inv;
}

// ---------------------------------------------------------------------------
extern "C" void kernel_launch(void* const* d_in, const int* in_sizes, int n_in,
                              void* d_out, int out_size)
{
    // metadata order: v,k,q, wq,bq, wk,bk, wv,bv, wo,bo
    const float* v  = (const float*)d_in[0];
    const float* k  = (const float*)d_in[1];
    const float* q  = (const float*)d_in[2];
    const float* wq = (const float*)d_in[3];
    const float* bq = (const float*)d_in[4];
    const float* wk = (const float*)d_in[5];
    const float* bk = (const float*)d_in[6];
    const float* wv = (const float*)d_in[7];
    const float* bv = (const float*)d_in[8];
    const float* wo = (const float*)d_in[9];
    const float* bo = (const float*)d_in[10];
    float* out = (float*)d_out;

    float *Qh, *KhT, *Vh, *Att, *Scr;
    cudaGetSymbolAddress((void**)&Qh,  g_Qh);
    cudaGetSymbolAddress((void**)&KhT, g_KhT);
    cudaGetSymbolAddress((void**)&Vh,  g_Vh);
    cudaGetSymbolAddress((void**)&Att, g_Att);
    cudaGetSymbolAddress((void**)&Scr, g_Scr);

    const long long sBH_qv = (long long)SEQ * DH;   // 131072
    const long long sBH_sc = (long long)SEQ * SEQ;  // 4194304

    // 1-3: QKV projections (4096x1024 @ 1024x1024), head-split epilogues
    {
        dim3 grid(DMODEL / 128, NROWS / 128, 1);
        gemm_k<1, 128, 8, 8><<<grid, 256>>>(q, wq, bq, Qh,  NROWS, DMODEL, DMODEL, 1.f, 0, 0, 0);
        gemm_k<2, 128, 8, 8><<<grid, 256>>>(k, wk, bk, KhT, NROWS, DMODEL, DMODEL, 1.f, 0, 0, 0);
        gemm_k<1, 128, 8, 8><<<grid, 256>>>(v, wv, bv, Vh,  NROWS, DMODEL, DMODEL, 1.f, 0, 0, 0);
    }

    // 4: scores = Qh @ KhT * 0.125 per (b,h)   (2048x2048, K=64)
    {
        dim3 grid(SEQ / 128, SEQ / 128, BATCH * HEADS);
        gemm_k<0, 128, 8, 8><<<grid, 256>>>(Qh, KhT, nullptr, Scr,
                                            SEQ, SEQ, DH, SCALE_QK,
                                            sBH_qv, sBH_qv, sBH_sc);
    }

    // 5: softmax over last dim
    softmax_rows<<<BATCH * HEADS * SEQ, 256>>>(Scr);

    // 6: Att = P @ Vh per (b,h)   (2048x64, K=2048), merged-head epilogue
    {
        dim3 grid(1, SEQ / 128, BATCH * HEADS);
        gemm_k<3, 64, 4, 8><<<grid, 256>>>(Scr, Vh, nullptr, Att,
                                           SEQ, DH, SEQ, 1.f,
                                           sBH_sc, sBH_qv, 0);
    }

    // 7: out = Att @ wo + bo  (4096x1024 @ 1024x1024)
    {
        dim3 grid(DMODEL / 128, NROWS / 128, 1);
        gemm_k<0, 128, 8, 8><<<grid, 256>>>(Att, wo, bo, out,
                                            NROWS, DMODEL, DMODEL, 1.f, 0, 0, 0);
    }
}

// round 7
// speedup vs baseline: 2.4883x; 2.4883x over previous
#include <cuda_runtime.h>
#include <cuda_bf16.h>
#include <math.h>
#include <stdint.h>

#define BATCH   2
#define SEQ     2048
#define DMODEL  1024
#define HEADS   16
#define DH      64
#define NROWS   (BATCH * SEQ)            // 4096
#define ZBH     (BATCH * HEADS)          // 32
#define SCALE_QK 0.125f

typedef __nv_bfloat16 bf16;

// ------------------------- device scratch (statics) -------------------------
__device__ bf16 g_q_hi[NROWS * DMODEL], g_q_lo[NROWS * DMODEL];
__device__ bf16 g_k_hi[NROWS * DMODEL], g_k_lo[NROWS * DMODEL];
__device__ bf16 g_v_hi[NROWS * DMODEL], g_v_lo[NROWS * DMODEL];

__device__ bf16 g_wqT_hi[DMODEL * DMODEL], g_wqT_lo[DMODEL * DMODEL];
__device__ bf16 g_wkT_hi[DMODEL * DMODEL], g_wkT_lo[DMODEL * DMODEL];
__device__ bf16 g_wvT_hi[DMODEL * DMODEL], g_wvT_lo[DMODEL * DMODEL];
__device__ bf16 g_woT_hi[DMODEL * DMODEL], g_woT_lo[DMODEL * DMODEL];

__device__ bf16 g_Qh_hi [ZBH * SEQ * DH], g_Qh_lo [ZBH * SEQ * DH];  // [b,h,s,d]
__device__ bf16 g_Kh_hi [ZBH * SEQ * DH], g_Kh_lo [ZBH * SEQ * DH];  // [b,h,s,d]
__device__ bf16 g_VhT_hi[ZBH * DH * SEQ], g_VhT_lo[ZBH * DH * SEQ];  // [b,h,d,s]

__device__ float g_Scr[(size_t)ZBH * SEQ * SEQ];                     // 512 MB
__device__ bf16  g_P_hi[(size_t)ZBH * SEQ * SEQ];                    // 256 MB
__device__ bf16  g_P_lo[(size_t)ZBH * SEQ * SEQ];                    // 256 MB

__device__ bf16 g_Att_hi[NROWS * DMODEL], g_Att_lo[NROWS * DMODEL];  // [b,s,h*d]

// ------------------------------- helpers ------------------------------------
__device__ __forceinline__ void split1(float x, bf16& h, bf16& l) {
    h = __float2bfloat16_rn(x);
    l = __float2bfloat16_rn(x - __bfloat162float(h));
}

__device__ __forceinline__ void cpasync16(bf16* dst, const bf16* src) {
    uint32_t d = (uint32_t)__cvta_generic_to_shared(dst);
    asm volatile("cp.async.cg.shared.global [%0], [%1], 16;\n" :: "r"(d), "l"(src));
}
__device__ __forceinline__ void cp_commit() {
    asm volatile("cp.async.commit_group;\n");
}
template<int N> __device__ __forceinline__ void cp_wait() {
    asm volatile("cp.async.wait_group %0;\n" :: "n"(N));
}

__device__ __forceinline__ void mma16816(float* c, const unsigned* a, const unsigned* b) {
    asm volatile(
        "mma.sync.aligned.m16n8k16.row.col.f32.bf16.bf16.f32 "
        "{%0,%1,%2,%3}, {%4,%5,%6,%7}, {%8,%9}, {%0,%1,%2,%3};"
        : "+f"(c[0]), "+f"(c[1]), "+f"(c[2]), "+f"(c[3])
        : "r"(a[0]), "r"(a[1]), "r"(a[2]), "r"(a[3]), "r"(b[0]), "r"(b[1]));
}

// ------------------------- split / transpose kernels ------------------------
__global__ void split_k(const float* __restrict__ x, bf16* __restrict__ hi,
                        bf16* __restrict__ lo, int n)
{
    for (int i = blockIdx.x * blockDim.x + threadIdx.x; i < n; i += gridDim.x * blockDim.x) {
        bf16 h, l; split1(x[i], h, l);
        hi[i] = h; lo[i] = l;
    }
}

// W [K=1024][N=1024] row-major -> WT[n][k] hi/lo
__global__ void tsplit_k(const float* __restrict__ W, bf16* __restrict__ hiT,
                         bf16* __restrict__ loT)
{
    __shared__ float t[32][33];
    const int bn = blockIdx.x * 32;   // n block
    const int bk = blockIdx.y * 32;   // k block
    for (int r = threadIdx.y; r < 32; r += 8)
        t[r][threadIdx.x] = W[(size_t)(bk + r) * DMODEL + bn + threadIdx.x];
    __syncthreads();
    for (int r = threadIdx.y; r < 32; r += 8) {
        float v = t[threadIdx.x][r];   // = W[bk+tx][bn+r]
        bf16 h, l; split1(v, h, l);
        size_t idx = (size_t)(bn + r) * DMODEL + bk + threadIdx.x;
        hiT[idx] = h; loT[idx] = l;
    }
}

// ---------------------------------------------------------------------------
// 3xBF16 tensor-core GEMM:  C = alpha*(A@Bop^T) + bias
//   A (hi/lo): M x K row-major, lda;  Bop (hi/lo): N x K row-major, ldb.
//   MODE 0: fp32 C [M x N] (+z*zC), optional bias
//   MODE 1: bf16 hi/lo head-split natural [b,h,s,d]
//   MODE 2: bf16 hi/lo head-split transposed [b,h,d,s]
//   MODE 3: bf16 hi/lo merged heads [b,s, h*DH + n]  (z = b*H + h)
// ---------------------------------------------------------------------------
template<int MODE, int BN>
__global__ void __launch_bounds__(256, 1)
gemm3(const bf16* __restrict__ Ah, const bf16* __restrict__ Al,
      const bf16* __restrict__ Bh, const bf16* __restrict__ Bl,
      const float* __restrict__ bias, void* Cv, void* C2v,
      int M, int N, int K, int lda, int ldb, float alpha,
      long long zA, long long zB, long long zC)
{
    constexpr int BM = 128, BK = 32;
    constexpr int PAD = 40;                 // padded row stride (elements)
    constexpr int A_STG = BM * PAD;
    constexpr int B_STG = BN * PAD;
    constexpr int WN = BN / 4;              // warp tile N
    constexpr int NFRAG = WN / 8;

    extern __shared__ bf16 sm[];
    bf16* sAh = sm;
    bf16* sAl = sm + 2 * A_STG;
    bf16* sBh = sm + 4 * A_STG;
    bf16* sBl = sBh + 2 * B_STG;

    const int z = blockIdx.z;
    const bf16* pAh = Ah + (size_t)z * zA;
    const bf16* pAl = Al + (size_t)z * zA;
    const bf16* pBh = Bh + (size_t)z * zB;
    const bf16* pBl = Bl + (size_t)z * zB;

    const int tid = threadIdx.x;
    const int lane = tid & 31, wid = tid >> 5;
    const int m0 = blockIdx.y * BM;
    const int n0 = blockIdx.x * BN;
    const int wm = (wid & 1) * 64;          // warp row base in tile
    const int wn = (wid >> 1) * WN;         // warp col base in tile
    const int g  = lane >> 2;
    const int tk = (lane & 3) * 2;

    float acc[4][NFRAG][4];
#pragma unroll
    for (int mi = 0; mi < 4; mi++)
#pragma unroll
        for (int ni = 0; ni < NFRAG; ni++)
#pragma unroll
            for (int r = 0; r < 4; r++) acc[mi][ni][r] = 0.f;

    auto stage_load = [&](int s, int kt) {
#pragma unroll
        for (int c = tid; c < BM * 4; c += 256) {
            int row = c >> 2, q = c & 3;
            size_t go = (size_t)(m0 + row) * lda + kt + q * 8;
            int so = s * A_STG + row * PAD + q * 8;
            cpasync16(sAh + so, pAh + go);
            cpasync16(sAl + so, pAl + go);
        }
#pragma unroll
        for (int c = tid; c < BN * 4; c += 256) {
            int row = c >> 2, q = c & 3;
            size_t go = (size_t)(n0 + row) * ldb + kt + q * 8;
            int so = s * B_STG + row * PAD + q * 8;
            cpasync16(sBh + so, pBh + go);
            cpasync16(sBl + so, pBl + go);
        }
        cp_commit();
    };

    auto compute = [&](int s) {
        const bf16* As_h = sAh + s * A_STG;
        const bf16* As_l = sAl + s * A_STG;
        const bf16* Bs_h = sBh + s * B_STG;
        const bf16* Bs_l = sBl + s * B_STG;
#pragma unroll
        for (int kh = 0; kh < 2; kh++) {
            const int kb = kh * 16;
            unsigned ah[4][4], al[4][4];
#pragma unroll
            for (int mi = 0; mi < 4; mi++) {
                int r = wm + mi * 16 + g;
                ah[mi][0] = *(const unsigned*)(As_h + r * PAD + kb + tk);
                ah[mi][1] = *(const unsigned*)(As_h + (r + 8) * PAD + kb + tk);
                ah[mi][2] = *(const unsigned*)(As_h + r * PAD + kb + tk + 8);
                ah[mi][3] = *(const unsigned*)(As_h + (r + 8) * PAD + kb + tk + 8);
                al[mi][0] = *(const unsigned*)(As_l + r * PAD + kb + tk);
                al[mi][1] = *(const unsigned*)(As_l + (r + 8) * PAD + kb + tk);
                al[mi][2] = *(const unsigned*)(As_l + r * PAD + kb + tk + 8);
                al[mi][3] = *(const unsigned*)(As_l + (r + 8) * PAD + kb + tk + 8);
            }
            unsigned bh[NFRAG][2], bl[NFRAG][2];
#pragma unroll
            for (int ni = 0; ni < NFRAG; ni++) {
                int n = wn + ni * 8 + g;
                bh[ni][0] = *(const unsigned*)(Bs_h + n * PAD + kb + tk);
                bh[ni][1] = *(const unsigned*)(Bs_h + n * PAD + kb + tk + 8);
                bl[ni][0] = *(const unsigned*)(Bs_l + n * PAD + kb + tk);
                bl[ni][1] = *(const unsigned*)(Bs_l + n * PAD + kb + tk + 8);
            }
#pragma unroll
            for (int mi = 0; mi < 4; mi++)
#pragma unroll
                for (int ni = 0; ni < NFRAG; ni++) {
                    mma16816(acc[mi][ni], ah[mi], bh[ni]);
                    mma16816(acc[mi][ni], ah[mi], bl[ni]);
                    mma16816(acc[mi][ni], al[mi], bh[ni]);
                }
        }
    };

    const int niter = K / BK;
    stage_load(0, 0);
    for (int it = 0; it < niter; it++) {
        if (it + 1 < niter) { stage_load((it + 1) & 1, (it + 1) * BK); cp_wait<1>(); }
        else                { cp_wait<0>(); }
        __syncthreads();
        compute(it & 1);
        __syncthreads();
    }

    // ------------------------------- epilogue -------------------------------
#pragma unroll
    for (int mi = 0; mi < 4; mi++)
#pragma unroll
        for (int ni = 0; ni < NFRAG; ni++)
#pragma unroll
            for (int half = 0; half < 2; half++) {
                const int r = m0 + wm + mi * 16 + g + half * 8;
                const int c = n0 + wn + ni * 8 + tk;
                float v0 = acc[mi][ni][half * 2 + 0] * alpha;
                float v1 = acc[mi][ni][half * 2 + 1] * alpha;
                if (bias) { v0 += bias[c]; v1 += bias[c + 1]; }

                if (MODE == 0) {
                    float* Cf = (float*)Cv + (size_t)z * zC;
                    float2 o; o.x = v0; o.y = v1;
                    *(float2*)&Cf[(size_t)r * N + c] = o;
                } else if (MODE == 1) {
                    int b = r >> 11, s = r & (SEQ - 1);
                    int h = c >> 6,  d = c & (DH - 1);
                    size_t idx = ((size_t)((b * HEADS + h) * SEQ + s)) * DH + d;
                    bf16 h0, l0, h1, l1; split1(v0, h0, l0); split1(v1, h1, l1);
                    __nv_bfloat162 th; th.x = h0; th.y = h1;
                    __nv_bfloat162 tl; tl.x = l0; tl.y = l1;
                    *(__nv_bfloat162*)((bf16*)Cv  + idx) = th;
                    *(__nv_bfloat162*)((bf16*)C2v + idx) = tl;
                } else if (MODE == 2) {
                    int b = r >> 11, s = r & (SEQ - 1);
                    int h = c >> 6,  d = c & (DH - 1);
                    size_t idx = ((size_t)((b * HEADS + h) * DH + d)) * SEQ + s;
                    bf16 h0, l0, h1, l1; split1(v0, h0, l0); split1(v1, h1, l1);
                    ((bf16*)Cv)[idx]        = h0;
                    ((bf16*)Cv)[idx + SEQ]  = h1;
                    ((bf16*)C2v)[idx]       = l0;
                    ((bf16*)C2v)[idx + SEQ] = l1;
                } else { // MODE 3
                    int b = z >> 4, h = z & (HEADS - 1);
                    size_t idx = ((size_t)(b * SEQ + r)) * DMODEL + h * DH + c;
                    bf16 h0, l0, h1, l1; split1(v0, h0, l0); split1(v1, h1, l1);
                    __nv_bfloat162 th; th.x = h0; th.y = h1;
                    __nv_bfloat162 tl; tl.x = l0; tl.y = l1;
                    *(__nv_bfloat162*)((bf16*)Cv  + idx) = th;
                    *(__nv_bfloat162*)((bf16*)C2v + idx) = tl;
                }
            }
}

// ----------------------- softmax (fp32 in, hi/lo bf16 out) ------------------
__global__ void __launch_bounds__(256)
softmax_k(const float* __restrict__ S, bf16* __restrict__ Ph, bf16* __restrict__ Pl)
{
    const size_t base = (size_t)blockIdx.x * SEQ;
    const float* p = S + base;
    const int tid = threadIdx.x;
    const int wid = tid >> 5, lid = tid & 31;
    __shared__ float red[8];

    float v[8];
#pragma unroll
    for (int i = 0; i < 8; i++) v[i] = p[tid + i * 256];

    float mx = v[0];
#pragma unroll
    for (int i = 1; i < 8; i++) mx = fmaxf(mx, v[i]);
#pragma unroll
    for (int o = 16; o; o >>= 1) mx = fmaxf(mx, __shfl_xor_sync(0xffffffffu, mx, o));
    if (lid == 0) red[wid] = mx;
    __syncthreads();
    float rmax = red[0];
#pragma unroll
    for (int w = 1; w < 8; w++) rmax = fmaxf(rmax, red[w]);
    __syncthreads();

    float s = 0.f;
#pragma unroll
    for (int i = 0; i < 8; i++) { v[i] = expf(v[i] - rmax); s += v[i]; }
#pragma unroll
    for (int o = 16; o; o >>= 1) s += __shfl_xor_sync(0xffffffffu, s, o);
    if (lid == 0) red[wid] = s;
    __syncthreads();
    float tot = 0.f;
#pragma unroll
    for (int w = 0; w < 8; w++) tot += red[w];
    const float inv = 1.f / tot;

#pragma unroll
    for (int i = 0; i < 8; i++) {
        bf16 h, l; split1(v[i] * inv, h, l);
        Ph[base + tid + i * 256] = h;
        Pl[base + tid + i * 256] = l;
    }
}

// ---------------------------------------------------------------------------
extern "C" void kernel_launch(void* const* d_in, const int* in_sizes, int n_in,
                              void* d_out, int out_size)
{
    const float* v  = (const float*)d_in[0];
    const float* k  = (const float*)d_in[1];
    const float* q  = (const float*)d_in[2];
    const float* wq = (const float*)d_in[3];
    const float* bq = (const float*)d_in[4];
    const float* wk = (const float*)d_in[5];
    const float* bk = (const float*)d_in[6];
    const float* wv = (const float*)d_in[7];
    const float* bv = (const float*)d_in[8];
    const float* wo = (const float*)d_in[9];
    const float* bo = (const float*)d_in[10];
    float* out = (float*)d_out;

    bf16 *q_hi, *q_lo, *k_hi, *k_lo, *v_hi, *v_lo;
    bf16 *wqT_hi, *wqT_lo, *wkT_hi, *wkT_lo, *wvT_hi, *wvT_lo, *woT_hi, *woT_lo;
    bf16 *Qh_hi, *Qh_lo, *Kh_hi, *Kh_lo, *VhT_hi, *VhT_lo;
    bf16 *P_hi, *P_lo, *Att_hi, *Att_lo;
    float* Scr;
    cudaGetSymbolAddress((void**)&q_hi,  g_q_hi);  cudaGetSymbolAddress((void**)&q_lo,  g_q_lo);
    cudaGetSymbolAddress((void**)&k_hi,  g_k_hi);  cudaGetSymbolAddress((void**)&k_lo,  g_k_lo);
    cudaGetSymbolAddress((void**)&v_hi,  g_v_hi);  cudaGetSymbolAddress((void**)&v_lo,  g_v_lo);
    cudaGetSymbolAddress((void**)&wqT_hi, g_wqT_hi); cudaGetSymbolAddress((void**)&wqT_lo, g_wqT_lo);
    cudaGetSymbolAddress((void**)&wkT_hi, g_wkT_hi); cudaGetSymbolAddress((void**)&wkT_lo, g_wkT_lo);
    cudaGetSymbolAddress((void**)&wvT_hi, g_wvT_hi); cudaGetSymbolAddress((void**)&wvT_lo, g_wvT_lo);
    cudaGetSymbolAddress((void**)&woT_hi, g_woT_hi); cudaGetSymbolAddress((void**)&woT_lo, g_woT_lo);
    cudaGetSymbolAddress((void**)&Qh_hi,  g_Qh_hi);  cudaGetSymbolAddress((void**)&Qh_lo,  g_Qh_lo);
    cudaGetSymbolAddress((void**)&Kh_hi,  g_Kh_hi);  cudaGetSymbolAddress((void**)&Kh_lo,  g_Kh_lo);
    cudaGetSymbolAddress((void**)&VhT_hi, g_VhT_hi); cudaGetSymbolAddress((void**)&VhT_lo, g_VhT_lo);
    cudaGetSymbolAddress((void**)&P_hi,   g_P_hi);   cudaGetSymbolAddress((void**)&P_lo,   g_P_lo);
    cudaGetSymbolAddress((void**)&Att_hi, g_Att_hi); cudaGetSymbolAddress((void**)&Att_lo, g_Att_lo);
    cudaGetSymbolAddress((void**)&Scr,    g_Scr);

    const size_t smem128 = (size_t)(4 * 128 * 40 + 4 * 128 * 40) * sizeof(bf16); // 81920
    const size_t smem64  = (size_t)(4 * 128 * 40 + 4 * 64  * 40) * sizeof(bf16); // 61440
    cudaFuncSetAttribute(gemm3<0, 128>, cudaFuncAttributeMaxDynamicSharedMemorySize, (int)smem128);
    cudaFuncSetAttribute(gemm3<1, 128>, cudaFuncAttributeMaxDynamicSharedMemorySize, (int)smem128);
    cudaFuncSetAttribute(gemm3<2, 128>, cudaFuncAttributeMaxDynamicSharedMemorySize, (int)smem128);
    cudaFuncSetAttribute(gemm3<3, 64>,  cudaFuncAttributeMaxDynamicSharedMemorySize, (int)smem64);

    // 1) split inputs + transpose/split weights
    split_k<<<1024, 256>>>(q, q_hi, q_lo, NROWS * DMODEL);
    split_k<<<1024, 256>>>(k, k_hi, k_lo, NROWS * DMODEL);
    split_k<<<1024, 256>>>(v, v_hi, v_lo, NROWS * DMODEL);
    {
        dim3 g(32, 32), b(32, 8);
        tsplit_k<<<g, b>>>(wq, wqT_hi, wqT_lo);
        tsplit_k<<<g, b>>>(wk, wkT_hi, wkT_lo);
        tsplit_k<<<g, b>>>(wv, wvT_hi, wvT_lo);
        tsplit_k<<<g, b>>>(wo, woT_hi, woT_lo);
    }

    const long long zQKv = (long long)SEQ * DH;     // Qh/Kh plane stride
    const long long zVT  = (long long)DH * SEQ;     // VhT plane stride
    const long long zSc  = (long long)SEQ * SEQ;    // score plane stride

    // 2) QKV projections: (4096x1024x1024), head-split epilogues
    {
        dim3 grid(DMODEL / 128, NROWS / 128, 1);
        gemm3<1, 128><<<grid, 256, smem128>>>(q_hi, q_lo, wqT_hi, wqT_lo, bq,
            Qh_hi, Qh_lo, NROWS, DMODEL, DMODEL, DMODEL, DMODEL, 1.f, 0, 0, 0);
        gemm3<1, 128><<<grid, 256, smem128>>>(k_hi, k_lo, wkT_hi, wkT_lo, bk,
            Kh_hi, Kh_lo, NROWS, DMODEL, DMODEL, DMODEL, DMODEL, 1.f, 0, 0, 0);
        gemm3<2, 128><<<grid, 256, smem128>>>(v_hi, v_lo, wvT_hi, wvT_lo, bv,
            VhT_hi, VhT_lo, NROWS, DMODEL, DMODEL, DMODEL, DMODEL, 1.f, 0, 0, 0);
    }

    // 3) scores = (Qh @ Kh^T) * 0.125, per (b,h): 2048x2048, K=64
    {
        dim3 grid(SEQ / 128, SEQ / 128, ZBH);
        gemm3<0, 128><<<grid, 256, smem128>>>(Qh_hi, Qh_lo, Kh_hi, Kh_lo, nullptr,
            Scr, nullptr, SEQ, SEQ, DH, DH, DH, SCALE_QK, zQKv, zQKv, zSc);
    }

    // 4) softmax -> P hi/lo
    softmax_k<<<ZBH * SEQ, 256>>>(Scr, P_hi, P_lo);

    // 5) Att = P @ V per (b,h): 2048x64, K=2048, merged-head epilogue
    {
        dim3 grid(1, SEQ / 128, ZBH);
        gemm3<3, 64><<<grid, 256, smem64>>>(P_hi, P_lo, VhT_hi, VhT_lo, nullptr,
            Att_hi, Att_lo, SEQ, DH, SEQ, SEQ, SEQ, 1.f, zSc, zVT, 0);
    }

    // 6) out = Att @ wo + bo: 4096x1024x1024, fp32 out
    {
        dim3 grid(DMODEL / 128, NROWS / 128, 1);
        gemm3<0, 128><<<grid, 256, smem128>>>(Att_hi, Att_lo, woT_hi, woT_lo, bo,
            out, nullptr, NROWS, DMODEL, DMODEL, DMODEL, DMODEL, 1.f, 0, 0, 0);
    }
}

// round 8
// speedup vs baseline: 3.4618x; 1.3912x over previous
#include <cuda_runtime.h>
#include <cuda_bf16.h>
#include <math.h>
#include <stdint.h>

#define BATCH   2
#define SEQ     2048
#define DMODEL  1024
#define HEADS   16
#define DH      64
#define NROWS   (BATCH * SEQ)            // 4096
#define ZBH     (BATCH * HEADS)          // 32
#define SCALE_QK 0.125f
// 0.125 * log2(e): softmax computed in exp2 domain
#define SCL2 0.1803368801111204f

typedef __nv_bfloat16 bf16;

// ------------------------- device scratch (statics) -------------------------
__device__ bf16 g_q_hi[NROWS * DMODEL], g_q_lo[NROWS * DMODEL];
__device__ bf16 g_k_hi[NROWS * DMODEL], g_k_lo[NROWS * DMODEL];
__device__ bf16 g_v_hi[NROWS * DMODEL], g_v_lo[NROWS * DMODEL];

__device__ bf16 g_wqT_hi[DMODEL * DMODEL], g_wqT_lo[DMODEL * DMODEL];
__device__ bf16 g_wkT_hi[DMODEL * DMODEL], g_wkT_lo[DMODEL * DMODEL];
__device__ bf16 g_wvT_hi[DMODEL * DMODEL], g_wvT_lo[DMODEL * DMODEL];
__device__ bf16 g_woT_hi[DMODEL * DMODEL], g_woT_lo[DMODEL * DMODEL];

__device__ bf16 g_Qh_hi [ZBH * SEQ * DH], g_Qh_lo [ZBH * SEQ * DH];  // [b,h,s,d]
__device__ bf16 g_Kh_hi [ZBH * SEQ * DH], g_Kh_lo [ZBH * SEQ * DH];  // [b,h,s,d]
__device__ bf16 g_VhT_hi[ZBH * DH * SEQ], g_VhT_lo[ZBH * DH * SEQ];  // [b,h,d,s]

__device__ bf16 g_Att_hi[NROWS * DMODEL], g_Att_lo[NROWS * DMODEL];  // [b,s,h*d]

// ------------------------------- helpers ------------------------------------
__device__ __forceinline__ void split1(float x, bf16& h, bf16& l) {
    h = __float2bfloat16_rn(x);
    l = __float2bfloat16_rn(x - __bfloat162float(h));
}
__device__ __forceinline__ void split2pack(float x0, float x1, unsigned& hi, unsigned& lo) {
    bf16 h0, l0, h1, l1;
    split1(x0, h0, l0); split1(x1, h1, l1);
    __nv_bfloat162 th; th.x = h0; th.y = h1;
    __nv_bfloat162 tl; tl.x = l0; tl.y = l1;
    hi = *(unsigned*)&th; lo = *(unsigned*)&tl;
}
__device__ __forceinline__ float ex2(float x) {
    float r;
    asm("ex2.approx.ftz.f32 %0, %1;" : "=f"(r) : "f"(x));
    return r;
}
__device__ __forceinline__ void cpasync16(bf16* dst, const bf16* src) {
    uint32_t d = (uint32_t)__cvta_generic_to_shared(dst);
    asm volatile("cp.async.cg.shared.global [%0], [%1], 16;\n" :: "r"(d), "l"(src));
}
__device__ __forceinline__ void cp_commit() { asm volatile("cp.async.commit_group;\n"); }
template<int N> __device__ __forceinline__ void cp_wait() {
    asm volatile("cp.async.wait_group %0;\n" :: "n"(N));
}
__device__ __forceinline__ void mma16816(float* c, const unsigned* a, const unsigned* b) {
    asm volatile(
        "mma.sync.aligned.m16n8k16.row.col.f32.bf16.bf16.f32 "
        "{%0,%1,%2,%3}, {%4,%5,%6,%7}, {%8,%9}, {%0,%1,%2,%3};"
        : "+f"(c[0]), "+f"(c[1]), "+f"(c[2]), "+f"(c[3])
        : "r"(a[0]), "r"(a[1]), "r"(a[2]), "r"(a[3]), "r"(b[0]), "r"(b[1]));
}

// ------------------------- split / transpose kernels ------------------------
__global__ void split_k(const float* __restrict__ x, bf16* __restrict__ hi,
                        bf16* __restrict__ lo, int n)
{
    for (int i = blockIdx.x * blockDim.x + threadIdx.x; i < n; i += gridDim.x * blockDim.x) {
        bf16 h, l; split1(x[i], h, l);
        hi[i] = h; lo[i] = l;
    }
}

__global__ void tsplit_k(const float* __restrict__ W, bf16* __restrict__ hiT,
                         bf16* __restrict__ loT)
{
    __shared__ float t[32][33];
    const int bn = blockIdx.x * 32;
    const int bk = blockIdx.y * 32;
    for (int r = threadIdx.y; r < 32; r += 8)
        t[r][threadIdx.x] = W[(size_t)(bk + r) * DMODEL + bn + threadIdx.x];
    __syncthreads();
    for (int r = threadIdx.y; r < 32; r += 8) {
        float v = t[threadIdx.x][r];
        bf16 h, l; split1(v, h, l);
        size_t idx = (size_t)(bn + r) * DMODEL + bk + threadIdx.x;
        hiT[idx] = h; loT[idx] = l;
    }
}

// ---------------------------------------------------------------------------
// 3xBF16 GEMM for the projections:  C = alpha*(A@B^T) + bias
// ---------------------------------------------------------------------------
template<int MODE, int BN>
__global__ void __launch_bounds__(256, 1)
gemm3(const bf16* __restrict__ Ah, const bf16* __restrict__ Al,
      const bf16* __restrict__ Bh, const bf16* __restrict__ Bl,
      const float* __restrict__ bias, void* Cv, void* C2v,
      int M, int N, int K, int lda, int ldb, float alpha,
      long long zA, long long zB, long long zC)
{
    constexpr int BM = 128, BK = 32;
    constexpr int PAD = 40;
    constexpr int A_STG = BM * PAD;
    constexpr int B_STG = BN * PAD;
    constexpr int WN = BN / 4;
    constexpr int NFRAG = WN / 8;

    extern __shared__ bf16 sm[];
    bf16* sAh = sm;
    bf16* sAl = sm + 2 * A_STG;
    bf16* sBh = sm + 4 * A_STG;
    bf16* sBl = sBh + 2 * B_STG;

    const int z = blockIdx.z;
    const bf16* pAh = Ah + (size_t)z * zA;
    const bf16* pAl = Al + (size_t)z * zA;
    const bf16* pBh = Bh + (size_t)z * zB;
    const bf16* pBl = Bl + (size_t)z * zB;

    const int tid = threadIdx.x;
    const int lane = tid & 31, wid = tid >> 5;
    const int m0 = blockIdx.y * BM;
    const int n0 = blockIdx.x * BN;
    const int wm = (wid & 1) * 64;
    const int wn = (wid >> 1) * WN;
    const int g  = lane >> 2;
    const int tk = (lane & 3) * 2;

    float acc[4][NFRAG][4];
#pragma unroll
    for (int mi = 0; mi < 4; mi++)
#pragma unroll
        for (int ni = 0; ni < NFRAG; ni++)
#pragma unroll
            for (int r = 0; r < 4; r++) acc[mi][ni][r] = 0.f;

    auto stage_load = [&](int s, int kt) {
#pragma unroll
        for (int c = tid; c < BM * 4; c += 256) {
            int row = c >> 2, q = c & 3;
            size_t go = (size_t)(m0 + row) * lda + kt + q * 8;
            int so = s * A_STG + row * PAD + q * 8;
            cpasync16(sAh + so, pAh + go);
            cpasync16(sAl + so, pAl + go);
        }
#pragma unroll
        for (int c = tid; c < BN * 4; c += 256) {
            int row = c >> 2, q = c & 3;
            size_t go = (size_t)(n0 + row) * ldb + kt + q * 8;
            int so = s * B_STG + row * PAD + q * 8;
            cpasync16(sBh + so, pBh + go);
            cpasync16(sBl + so, pBl + go);
        }
        cp_commit();
    };

    auto compute = [&](int s) {
        const bf16* As_h = sAh + s * A_STG;
        const bf16* As_l = sAl + s * A_STG;
        const bf16* Bs_h = sBh + s * B_STG;
        const bf16* Bs_l = sBl + s * B_STG;
#pragma unroll
        for (int kh = 0; kh < 2; kh++) {
            const int kb = kh * 16;
            unsigned ah[4][4], al[4][4];
#pragma unroll
            for (int mi = 0; mi < 4; mi++) {
                int r = wm + mi * 16 + g;
                ah[mi][0] = *(const unsigned*)(As_h + r * PAD + kb + tk);
                ah[mi][1] = *(const unsigned*)(As_h + (r + 8) * PAD + kb + tk);
                ah[mi][2] = *(const unsigned*)(As_h + r * PAD + kb + tk + 8);
                ah[mi][3] = *(const unsigned*)(As_h + (r + 8) * PAD + kb + tk + 8);
                al[mi][0] = *(const unsigned*)(As_l + r * PAD + kb + tk);
                al[mi][1] = *(const unsigned*)(As_l + (r + 8) * PAD + kb + tk);
                al[mi][2] = *(const unsigned*)(As_l + r * PAD + kb + tk + 8);
                al[mi][3] = *(const unsigned*)(As_l + (r + 8) * PAD + kb + tk + 8);
            }
            unsigned bh[NFRAG][2], bl[NFRAG][2];
#pragma unroll
            for (int ni = 0; ni < NFRAG; ni++) {
                int n = wn + ni * 8 + g;
                bh[ni][0] = *(const unsigned*)(Bs_h + n * PAD + kb + tk);
                bh[ni][1] = *(const unsigned*)(Bs_h + n * PAD + kb + tk + 8);
                bl[ni][0] = *(const unsigned*)(Bs_l + n * PAD + kb + tk);
                bl[ni][1] = *(const unsigned*)(Bs_l + n * PAD + kb + tk + 8);
            }
#pragma unroll
            for (int mi = 0; mi < 4; mi++)
#pragma unroll
                for (int ni = 0; ni < NFRAG; ni++) {
                    mma16816(acc[mi][ni], ah[mi], bh[ni]);
                    mma16816(acc[mi][ni], ah[mi], bl[ni]);
                    mma16816(acc[mi][ni], al[mi], bh[ni]);
                }
        }
    };

    const int niter = K / BK;
    stage_load(0, 0);
    for (int it = 0; it < niter; it++) {
        if (it + 1 < niter) { stage_load((it + 1) & 1, (it + 1) * BK); cp_wait<1>(); }
        else                { cp_wait<0>(); }
        __syncthreads();
        compute(it & 1);
        __syncthreads();
    }

#pragma unroll
    for (int mi = 0; mi < 4; mi++)
#pragma unroll
        for (int ni = 0; ni < NFRAG; ni++)
#pragma unroll
            for (int half = 0; half < 2; half++) {
                const int r = m0 + wm + mi * 16 + g + half * 8;
                const int c = n0 + wn + ni * 8 + tk;
                float v0 = acc[mi][ni][half * 2 + 0] * alpha;
                float v1 = acc[mi][ni][half * 2 + 1] * alpha;
                if (bias) { v0 += bias[c]; v1 += bias[c + 1]; }

                if (MODE == 0) {
                    float* Cf = (float*)Cv + (size_t)z * zC;
                    float2 o; o.x = v0; o.y = v1;
                    *(float2*)&Cf[(size_t)r * N + c] = o;
                } else if (MODE == 1) {
                    int b = r >> 11, s = r & (SEQ - 1);
                    int h = c >> 6,  d = c & (DH - 1);
                    size_t idx = ((size_t)((b * HEADS + h) * SEQ + s)) * DH + d;
                    unsigned uh, ul; split2pack(v0, v1, uh, ul);
                    *(unsigned*)((bf16*)Cv  + idx) = uh;
                    *(unsigned*)((bf16*)C2v + idx) = ul;
                } else if (MODE == 2) {
                    int b = r >> 11, s = r & (SEQ - 1);
                    int h = c >> 6,  d = c & (DH - 1);
                    size_t idx = ((size_t)((b * HEADS + h) * DH + d)) * SEQ + s;
                    bf16 h0, l0, h1, l1; split1(v0, h0, l0); split1(v1, h1, l1);
                    ((bf16*)Cv)[idx]        = h0;
                    ((bf16*)Cv)[idx + SEQ]  = h1;
                    ((bf16*)C2v)[idx]       = l0;
                    ((bf16*)C2v)[idx + SEQ] = l1;
                }
            }
}

// ---------------------------------------------------------------------------
// Fused flash attention, 3xbf16 emulation.
//   Grid: (SEQ/128, ZBH). 256 threads = 8 warps x 16 Q-rows.
//   K chunk: [128 keys][64 d] hi/lo ; V chunk: [64 d][128 keys] hi/lo.
//   Q fragments register-resident; P stays in registers (C->A frag identity).
// ---------------------------------------------------------------------------
__global__ void __launch_bounds__(256, 1)
flash_attn(const bf16* __restrict__ Qh, const bf16* __restrict__ Ql,
           const bf16* __restrict__ Kh, const bf16* __restrict__ Kl,
           const bf16* __restrict__ Vh, const bf16* __restrict__ Vl,
           bf16* __restrict__ Oh, bf16* __restrict__ Ol)
{
    constexpr int PADK = 72, PADV = 136;
    constexpr int KSTG = 128 * PADK, VSTG = 64 * PADV;
    extern __shared__ bf16 sm[];
    bf16* sKh = sm;                 // [2][KSTG]
    bf16* sKl = sm + 2 * KSTG;
    bf16* sVh = sm + 4 * KSTG;      // [2][VSTG]
    bf16* sVl = sVh + 2 * VSTG;

    const int z = blockIdx.y;
    const bf16* pQh = Qh + (size_t)z * SEQ * DH;
    const bf16* pQl = Ql + (size_t)z * SEQ * DH;
    const bf16* pKh = Kh + (size_t)z * SEQ * DH;
    const bf16* pKl = Kl + (size_t)z * SEQ * DH;
    const bf16* pVh = Vh + (size_t)z * DH * SEQ;
    const bf16* pVl = Vl + (size_t)z * DH * SEQ;

    const int tid = threadIdx.x;
    const int lane = tid & 31, wid = tid >> 5;
    const int g = lane >> 2, tk = (lane & 3) * 2;
    const int r0 = blockIdx.x * 128 + wid * 16 + g;   // rows r0, r0+8

    // Q fragments (register-resident)
    unsigned aQh[4][4], aQl[4][4];
#pragma unroll
    for (int kk = 0; kk < 4; kk++) {
        int kc = kk * 16 + tk;
        aQh[kk][0] = *(const unsigned*)&pQh[(size_t)r0 * DH + kc];
        aQh[kk][1] = *(const unsigned*)&pQh[(size_t)(r0 + 8) * DH + kc];
        aQh[kk][2] = *(const unsigned*)&pQh[(size_t)r0 * DH + kc + 8];
        aQh[kk][3] = *(const unsigned*)&pQh[(size_t)(r0 + 8) * DH + kc + 8];
        aQl[kk][0] = *(const unsigned*)&pQl[(size_t)r0 * DH + kc];
        aQl[kk][1] = *(const unsigned*)&pQl[(size_t)(r0 + 8) * DH + kc];
        aQl[kk][2] = *(const unsigned*)&pQl[(size_t)r0 * DH + kc + 8];
        aQl[kk][3] = *(const unsigned*)&pQl[(size_t)(r0 + 8) * DH + kc + 8];
    }

    auto stage_load = [&](int s, int kv0) {
#pragma unroll
        for (int c = tid; c < 1024; c += 256) {         // K chunk: 128x64
            int row = c >> 3, qd = (c & 7) * 8;
            size_t go = (size_t)(kv0 + row) * DH + qd;
            int so = s * KSTG + row * PADK + qd;
            cpasync16(sKh + so, pKh + go);
            cpasync16(sKl + so, pKl + go);
        }
#pragma unroll
        for (int c = tid; c < 1024; c += 256) {         // V chunk: 64x128
            int d = c >> 4, qd = (c & 15) * 8;
            size_t go = (size_t)d * SEQ + kv0 + qd;
            int so = s * VSTG + d * PADV + qd;
            cpasync16(sVh + so, pVh + go);
            cpasync16(sVl + so, pVl + go);
        }
        cp_commit();
    };

    float m0 = -1e30f, m1 = -1e30f, l0 = 0.f, l1 = 0.f;
    float oacc[8][4];
#pragma unroll
    for (int dn = 0; dn < 8; dn++)
#pragma unroll
        for (int r = 0; r < 4; r++) oacc[dn][r] = 0.f;

    stage_load(0, 0);
    for (int it = 0; it < SEQ / 128; it++) {
        if (it + 1 < SEQ / 128) { stage_load((it + 1) & 1, (it + 1) * 128); cp_wait<1>(); }
        else                    { cp_wait<0>(); }
        __syncthreads();

        const bf16* Ksh = sKh + (it & 1) * KSTG;
        const bf16* Ksl = sKl + (it & 1) * KSTG;
        const bf16* Vsh = sVh + (it & 1) * VSTG;
        const bf16* Vsl = sVl + (it & 1) * VSTG;

        // ---- S = Q @ K^T (16 rows x 128 keys per warp), fp32 C frags ----
        float sacc[16][4];
#pragma unroll
        for (int nj = 0; nj < 16; nj++) {
#pragma unroll
            for (int r = 0; r < 4; r++) sacc[nj][r] = 0.f;
        }
#pragma unroll
        for (int nj = 0; nj < 16; nj++) {
            const bf16* kh_ = Ksh + (nj * 8 + g) * PADK + tk;
            const bf16* kl_ = Ksl + (nj * 8 + g) * PADK + tk;
#pragma unroll
            for (int kk = 0; kk < 4; kk++) {
                unsigned bh[2], bl[2];
                bh[0] = *(const unsigned*)(kh_ + kk * 16);
                bh[1] = *(const unsigned*)(kh_ + kk * 16 + 8);
                bl[0] = *(const unsigned*)(kl_ + kk * 16);
                bl[1] = *(const unsigned*)(kl_ + kk * 16 + 8);
                mma16816(sacc[nj], aQh[kk], bh);
                mma16816(sacc[nj], aQh[kk], bl);
                mma16816(sacc[nj], aQl[kk], bh);
            }
        }

        // ---- online softmax (exp2 domain, scale folded) ----
        float cm0 = -1e30f, cm1 = -1e30f;
#pragma unroll
        for (int nj = 0; nj < 16; nj++) {
            sacc[nj][0] *= SCL2; sacc[nj][1] *= SCL2;
            sacc[nj][2] *= SCL2; sacc[nj][3] *= SCL2;
            cm0 = fmaxf(cm0, fmaxf(sacc[nj][0], sacc[nj][1]));
            cm1 = fmaxf(cm1, fmaxf(sacc[nj][2], sacc[nj][3]));
        }
        cm0 = fmaxf(cm0, __shfl_xor_sync(0xffffffffu, cm0, 1));
        cm0 = fmaxf(cm0, __shfl_xor_sync(0xffffffffu, cm0, 2));
        cm1 = fmaxf(cm1, __shfl_xor_sync(0xffffffffu, cm1, 1));
        cm1 = fmaxf(cm1, __shfl_xor_sync(0xffffffffu, cm1, 2));
        float mn0 = fmaxf(m0, cm0), mn1 = fmaxf(m1, cm1);
        float f0 = ex2(m0 - mn0), f1 = ex2(m1 - mn1);
        m0 = mn0; m1 = mn1;

        float ps0 = 0.f, ps1 = 0.f;
#pragma unroll
        for (int nj = 0; nj < 16; nj++) {
            sacc[nj][0] = ex2(sacc[nj][0] - mn0);
            sacc[nj][1] = ex2(sacc[nj][1] - mn0);
            sacc[nj][2] = ex2(sacc[nj][2] - mn1);
            sacc[nj][3] = ex2(sacc[nj][3] - mn1);
            ps0 += sacc[nj][0] + sacc[nj][1];
            ps1 += sacc[nj][2] + sacc[nj][3];
        }
        ps0 += __shfl_xor_sync(0xffffffffu, ps0, 1);
        ps0 += __shfl_xor_sync(0xffffffffu, ps0, 2);
        ps1 += __shfl_xor_sync(0xffffffffu, ps1, 1);
        ps1 += __shfl_xor_sync(0xffffffffu, ps1, 2);
        l0 = l0 * f0 + ps0;
        l1 = l1 * f1 + ps1;

#pragma unroll
        for (int dn = 0; dn < 8; dn++) {
            oacc[dn][0] *= f0; oacc[dn][1] *= f0;
            oacc[dn][2] *= f1; oacc[dn][3] *= f1;
        }

        // ---- O += P @ V  (P: C->A fragment identity, split hi/lo on the fly) ----
#pragma unroll
        for (int kk = 0; kk < 8; kk++) {
            unsigned ah_[4], al_[4];
            const int t0 = 2 * kk, t1 = 2 * kk + 1;
            split2pack(sacc[t0][0], sacc[t0][1], ah_[0], al_[0]);
            split2pack(sacc[t0][2], sacc[t0][3], ah_[1], al_[1]);
            split2pack(sacc[t1][0], sacc[t1][1], ah_[2], al_[2]);
            split2pack(sacc[t1][2], sacc[t1][3], ah_[3], al_[3]);
#pragma unroll
            for (int dn = 0; dn < 8; dn++) {
                const bf16* vh_ = Vsh + (dn * 8 + g) * PADV + kk * 16 + tk;
                const bf16* vl_ = Vsl + (dn * 8 + g) * PADV + kk * 16 + tk;
                unsigned bh[2], bl[2];
                bh[0] = *(const unsigned*)(vh_);
                bh[1] = *(const unsigned*)(vh_ + 8);
                bl[0] = *(const unsigned*)(vl_);
                bl[1] = *(const unsigned*)(vl_ + 8);
                mma16816(oacc[dn], ah_, bh);
                mma16816(oacc[dn], ah_, bl);
                mma16816(oacc[dn], al_, bh);
            }
        }
        __syncthreads();
    }

    // ---- epilogue: O /= l, split to hi/lo, write merged-head layout ----
    const float inv0 = 1.f / l0, inv1 = 1.f / l1;
    const int b = z >> 4, h = z & (HEADS - 1);
#pragma unroll
    for (int dn = 0; dn < 8; dn++) {
        const int c = h * DH + dn * 8 + tk;
        size_t i0 = ((size_t)(b * SEQ + r0)) * DMODEL + c;
        size_t i1 = ((size_t)(b * SEQ + r0 + 8)) * DMODEL + c;
        unsigned uh, ul;
        split2pack(oacc[dn][0] * inv0, oacc[dn][1] * inv0, uh, ul);
        *(unsigned*)(Oh + i0) = uh; *(unsigned*)(Ol + i0) = ul;
        split2pack(oacc[dn][2] * inv1, oacc[dn][3] * inv1, uh, ul);
        *(unsigned*)(Oh + i1) = uh; *(unsigned*)(Ol + i1) = ul;
    }
}

// ---------------------------------------------------------------------------
extern "C" void kernel_launch(void* const* d_in, const int* in_sizes, int n_in,
                              void* d_out, int out_size)
{
    const float* v  = (const float*)d_in[0];
    const float* k  = (const float*)d_in[1];
    const float* q  = (const float*)d_in[2];
    const float* wq = (const float*)d_in[3];
    const float* bq = (const float*)d_in[4];
    const float* wk = (const float*)d_in[5];
    const float* bk = (const float*)d_in[6];
    const float* wv = (const float*)d_in[7];
    const float* bv = (const float*)d_in[8];
    const float* wo = (const float*)d_in[9];
    const float* bo = (const float*)d_in[10];
    float* out = (float*)d_out;

    bf16 *q_hi, *q_lo, *k_hi, *k_lo, *v_hi, *v_lo;
    bf16 *wqT_hi, *wqT_lo, *wkT_hi, *wkT_lo, *wvT_hi, *wvT_lo, *woT_hi, *woT_lo;
    bf16 *Qh_hi, *Qh_lo, *Kh_hi, *Kh_lo, *VhT_hi, *VhT_lo, *Att_hi, *Att_lo;
    cudaGetSymbolAddress((void**)&q_hi,  g_q_hi);  cudaGetSymbolAddress((void**)&q_lo,  g_q_lo);
    cudaGetSymbolAddress((void**)&k_hi,  g_k_hi);  cudaGetSymbolAddress((void**)&k_lo,  g_k_lo);
    cudaGetSymbolAddress((void**)&v_hi,  g_v_hi);  cudaGetSymbolAddress((void**)&v_lo,  g_v_lo);
    cudaGetSymbolAddress((void**)&wqT_hi, g_wqT_hi); cudaGetSymbolAddress((void**)&wqT_lo, g_wqT_lo);
    cudaGetSymbolAddress((void**)&wkT_hi, g_wkT_hi); cudaGetSymbolAddress((void**)&wkT_lo, g_wkT_lo);
    cudaGetSymbolAddress((void**)&wvT_hi, g_wvT_hi); cudaGetSymbolAddress((void**)&wvT_lo, g_wvT_lo);
    cudaGetSymbolAddress((void**)&woT_hi, g_woT_hi); cudaGetSymbolAddress((void**)&woT_lo, g_woT_lo);
    cudaGetSymbolAddress((void**)&Qh_hi,  g_Qh_hi);  cudaGetSymbolAddress((void**)&Qh_lo,  g_Qh_lo);
    cudaGetSymbolAddress((void**)&Kh_hi,  g_Kh_hi);  cudaGetSymbolAddress((void**)&Kh_lo,  g_Kh_lo);
    cudaGetSymbolAddress((void**)&VhT_hi, g_VhT_hi); cudaGetSymbolAddress((void**)&VhT_lo, g_VhT_lo);
    cudaGetSymbolAddress((void**)&Att_hi, g_Att_hi); cudaGetSymbolAddress((void**)&Att_lo, g_Att_lo);

    const size_t smem128 = (size_t)(8 * 128 * 40) * sizeof(bf16);                 // 81920
    const size_t smemFA  = (size_t)(4 * 128 * 72 + 4 * 64 * 136) * sizeof(bf16);  // 143360
    cudaFuncSetAttribute(gemm3<0, 128>, cudaFuncAttributeMaxDynamicSharedMemorySize, (int)smem128);
    cudaFuncSetAttribute(gemm3<1, 128>, cudaFuncAttributeMaxDynamicSharedMemorySize, (int)smem128);
    cudaFuncSetAttribute(gemm3<2, 128>, cudaFuncAttributeMaxDynamicSharedMemorySize, (int)smem128);
    cudaFuncSetAttribute(flash_attn,    cudaFuncAttributeMaxDynamicSharedMemorySize, (int)smemFA);

    // 1) split inputs + transpose/split weights
    split_k<<<1024, 256>>>(q, q_hi, q_lo, NROWS * DMODEL);
    split_k<<<1024, 256>>>(k, k_hi, k_lo, NROWS * DMODEL);
    split_k<<<1024, 256>>>(v, v_hi, v_lo, NROWS * DMODEL);
    {
        dim3 g(32, 32), b(32, 8);
        tsplit_k<<<g, b>>>(wq, wqT_hi, wqT_lo);
        tsplit_k<<<g, b>>>(wk, wkT_hi, wkT_lo);
        tsplit_k<<<g, b>>>(wv, wvT_hi, wvT_lo);
        tsplit_k<<<g, b>>>(wo, woT_hi, woT_lo);
    }

    // 2) QKV projections with head-split epilogues
    {
        dim3 grid(DMODEL / 128, NROWS / 128, 1);
        gemm3<1, 128><<<grid, 256, smem128>>>(q_hi, q_lo, wqT_hi, wqT_lo, bq,
            Qh_hi, Qh_lo, NROWS, DMODEL, DMODEL, DMODEL, DMODEL, 1.f, 0, 0, 0);
        gemm3<1, 128><<<grid, 256, smem128>>>(k_hi, k_lo, wkT_hi, wkT_lo, bk,
            Kh_hi, Kh_lo, NROWS, DMODEL, DMODEL, DMODEL, DMODEL, 1.f, 0, 0, 0);
        gemm3<2, 128><<<grid, 256, smem128>>>(v_hi, v_lo, wvT_hi, wvT_lo, bv,
            VhT_hi, VhT_lo, NROWS, DMODEL, DMODEL, DMODEL, DMODEL, 1.f, 0, 0, 0);
    }

    // 3) fused attention (QK^T -> online softmax -> PV), Att hi/lo out
    {
        dim3 grid(SEQ / 128, ZBH);
        flash_attn<<<grid, 256, smemFA>>>(Qh_hi, Qh_lo, Kh_hi, Kh_lo,
                                          VhT_hi, VhT_lo, Att_hi, Att_lo);
    }

    // 4) out = Att @ wo + bo (fp32 out)
    {
        dim3 grid(DMODEL / 128, NROWS / 128, 1);
        gemm3<0, 128><<<grid, 256, smem128>>>(Att_hi, Att_lo, woT_hi, woT_lo, bo,
            out, nullptr, NROWS, DMODEL, DMODEL, DMODEL, DMODEL, 1.f, 0, 0, 0);
    }
}

// round 10
// speedup vs baseline: 3.5251x; 1.0183x over previous
#include <cuda_runtime.h>
#include <cuda_bf16.h>
#include <math.h>
#include <stdint.h>

#define BATCH   2
#define SEQ     2048
#define DMODEL  1024
#define HEADS   16
#define DH      64
#define NROWS   (BATCH * SEQ)            // 4096
#define ZBH     (BATCH * HEADS)          // 32
#define SCALE_QK 0.125f
#define SCL2 0.1803368801111204f         // 0.125 * log2(e)

typedef __nv_bfloat16 bf16;

// ------------------------- device scratch (statics) -------------------------
__device__ bf16 g_q_hi[NROWS * DMODEL], g_q_lo[NROWS * DMODEL];
__device__ bf16 g_k_hi[NROWS * DMODEL], g_k_lo[NROWS * DMODEL];
__device__ bf16 g_v_hi[NROWS * DMODEL], g_v_lo[NROWS * DMODEL];

__device__ bf16 g_wqT_hi[DMODEL * DMODEL], g_wqT_lo[DMODEL * DMODEL];
__device__ bf16 g_wkT_hi[DMODEL * DMODEL], g_wkT_lo[DMODEL * DMODEL];
__device__ bf16 g_wvT_hi[DMODEL * DMODEL], g_wvT_lo[DMODEL * DMODEL];
__device__ bf16 g_woT_hi[DMODEL * DMODEL], g_woT_lo[DMODEL * DMODEL];

__device__ bf16 g_Qh_hi [ZBH * SEQ * DH], g_Qh_lo [ZBH * SEQ * DH];  // [b,h,s,d]
__device__ bf16 g_Kh_hi [ZBH * SEQ * DH], g_Kh_lo [ZBH * SEQ * DH];  // [b,h,s,d]
__device__ bf16 g_VhT_hi[ZBH * DH * SEQ], g_VhT_lo[ZBH * DH * SEQ];  // [b,h,d,s]

__device__ bf16 g_Att_hi[NROWS * DMODEL], g_Att_lo[NROWS * DMODEL];  // [b,s,h*d]

// ------------------------------- helpers ------------------------------------
__device__ __forceinline__ void split1(float x, bf16& h, bf16& l) {
    h = __float2bfloat16_rn(x);
    l = __float2bfloat16_rn(x - __bfloat162float(h));
}
__device__ __forceinline__ void split2pack(float x0, float x1, unsigned& hi, unsigned& lo) {
    bf16 h0, l0, h1, l1;
    split1(x0, h0, l0); split1(x1, h1, l1);
    __nv_bfloat162 th; th.x = h0; th.y = h1;
    __nv_bfloat162 tl; tl.x = l0; tl.y = l1;
    hi = *(unsigned*)&th; lo = *(unsigned*)&tl;
}
__device__ __forceinline__ float ex2(float x) {
    float r;
    asm("ex2.approx.ftz.f32 %0, %1;" : "=f"(r) : "f"(x));
    return r;
}
__device__ __forceinline__ void cpasync16(bf16* dst, const bf16* src) {
    uint32_t d = (uint32_t)__cvta_generic_to_shared(dst);
    asm volatile("cp.async.cg.shared.global [%0], [%1], 16;\n" :: "r"(d), "l"(src));
}
__device__ __forceinline__ void cp_commit() { asm volatile("cp.async.commit_group;\n"); }
template<int N> __device__ __forceinline__ void cp_wait() {
    asm volatile("cp.async.wait_group %0;\n" :: "n"(N));
}
__device__ __forceinline__ void mma16816(float* c, const unsigned* a, const unsigned* b) {
    asm volatile(
        "mma.sync.aligned.m16n8k16.row.col.f32.bf16.bf16.f32 "
        "{%0,%1,%2,%3}, {%4,%5,%6,%7}, {%8,%9}, {%0,%1,%2,%3};"
        : "+f"(c[0]), "+f"(c[1]), "+f"(c[2]), "+f"(c[3])
        : "r"(a[0]), "r"(a[1]), "r"(a[2]), "r"(a[3]), "r"(b[0]), "r"(b[1]));
}
__device__ __forceinline__ void ldm_x4(unsigned* r, uint32_t addr) {
    asm volatile("ldmatrix.sync.aligned.m8n8.x4.shared.b16 {%0,%1,%2,%3}, [%4];"
        : "=r"(r[0]), "=r"(r[1]), "=r"(r[2]), "=r"(r[3]) : "r"(addr));
}
__device__ __forceinline__ void ldm_x2(unsigned* r, uint32_t addr) {
    asm volatile("ldmatrix.sync.aligned.m8n8.x2.shared.b16 {%0,%1}, [%2];"
        : "=r"(r[0]), "=r"(r[1]) : "r"(addr));
}

// ------------------------- split / transpose kernels ------------------------
__global__ void split_k(const float* __restrict__ x, bf16* __restrict__ hi,
                        bf16* __restrict__ lo, int n)
{
    for (int i = blockIdx.x * blockDim.x + threadIdx.x; i < n; i += gridDim.x * blockDim.x) {
        bf16 h, l; split1(x[i], h, l);
        hi[i] = h; lo[i] = l;
    }
}

__global__ void tsplit_k(const float* __restrict__ W, bf16* __restrict__ hiT,
                         bf16* __restrict__ loT)
{
    __shared__ float t[32][33];
    const int bn = blockIdx.x * 32;
    const int bk = blockIdx.y * 32;
    for (int r = threadIdx.y; r < 32; r += 8)
        t[r][threadIdx.x] = W[(size_t)(bk + r) * DMODEL + bn + threadIdx.x];
    __syncthreads();
    for (int r = threadIdx.y; r < 32; r += 8) {
        float v = t[threadIdx.x][r];
        bf16 h, l; split1(v, h, l);
        size_t idx = (size_t)(bn + r) * DMODEL + bk + threadIdx.x;
        hiT[idx] = h; loT[idx] = l;
    }
}

// ---------------------------------------------------------------------------
// 3xBF16 GEMM (mma.sync + ldmatrix):  C = (A@B^T) + bias
//   A (hi/lo): M x K row-major; B (hi/lo): N x K row-major.
//   BM=128, BN=128, BK=32; 256 threads; warp tile 64x32.
//   MODE 0: fp32 C row-major; MODE 1: bf16 hi/lo [b,h,s,d]; MODE 2: [b,h,d,s]
// ---------------------------------------------------------------------------
template<int MODE>
__global__ void __launch_bounds__(256, 1)
gemm3(const bf16* __restrict__ Ah, const bf16* __restrict__ Al,
      const bf16* __restrict__ Bh, const bf16* __restrict__ Bl,
      const float* __restrict__ bias, void* Cv, void* C2v)
{
    constexpr int BM = 128, BN = 128, BK = 32;
    constexpr int PAD = 40;
    constexpr int A_STG = BM * PAD;
    constexpr int B_STG = BN * PAD;
    constexpr int NFRAG = 4;              // 32-wide warp N tile / 8

    extern __shared__ bf16 sm[];
    bf16* sAh = sm;
    bf16* sAl = sm + 2 * A_STG;
    bf16* sBh = sm + 4 * A_STG;
    bf16* sBl = sBh + 2 * B_STG;
    const uint32_t usm = (uint32_t)__cvta_generic_to_shared(sm);

    const int tid = threadIdx.x;
    const int lane = tid & 31, wid = tid >> 5;
    const int m0 = blockIdx.y * BM;
    const int n0 = blockIdx.x * BN;
    const int wm = (wid & 1) * 64;
    const int wn = (wid >> 1) * 32;
    const int g  = lane >> 2;
    const int tk = (lane & 3) * 2;

    // ldmatrix lane->address mapping
    const int lq = lane >> 3, li = lane & 7;
    const int a_row = (lq & 1) * 8 + li;   // + wm + mi*16
    const int a_col = (lq >> 1) * 8;       // + kb
    const int b_row = li;                  // + wn + ni*8
    const int b_col = (lq & 1) * 8;        // + kb (x2 uses lanes 0-15)

    float acc[4][NFRAG][4];
#pragma unroll
    for (int mi = 0; mi < 4; mi++)
#pragma unroll
        for (int ni = 0; ni < NFRAG; ni++)
#pragma unroll
            for (int r = 0; r < 4; r++) acc[mi][ni][r] = 0.f;

    auto stage_load = [&](int s, int kt) {
#pragma unroll
        for (int c = tid; c < BM * 4; c += 256) {
            int row = c >> 2, q = c & 3;
            size_t go = (size_t)(m0 + row) * DMODEL + kt + q * 8;
            int so = s * A_STG + row * PAD + q * 8;
            cpasync16(sAh + so, Ah + go);
            cpasync16(sAl + so, Al + go);
        }
#pragma unroll
        for (int c = tid; c < BN * 4; c += 256) {
            int row = c >> 2, q = c & 3;
            size_t go = (size_t)(n0 + row) * DMODEL + kt + q * 8;
            int so = s * B_STG + row * PAD + q * 8;
            cpasync16(sBh + so, Bh + go);
            cpasync16(sBl + so, Bl + go);
        }
        cp_commit();
    };

    auto compute = [&](int s) {
        const uint32_t aH = usm + 2u * (unsigned)(s * A_STG);
        const uint32_t aL = usm + 2u * (unsigned)(2 * A_STG + s * A_STG);
        const uint32_t bH = usm + 2u * (unsigned)(4 * A_STG + s * B_STG);
        const uint32_t bL = usm + 2u * (unsigned)(4 * A_STG + 2 * B_STG + s * B_STG);
#pragma unroll
        for (int kh = 0; kh < 2; kh++) {
            const int kb = kh * 16;
            unsigned ah[4][4], al[4][4];
#pragma unroll
            for (int mi = 0; mi < 4; mi++) {
                uint32_t off = 2u * (unsigned)((wm + mi * 16 + a_row) * PAD + kb + a_col);
                ldm_x4(ah[mi], aH + off);
                ldm_x4(al[mi], aL + off);
            }
            unsigned bh[NFRAG][2], bl[NFRAG][2];
#pragma unroll
            for (int ni = 0; ni < NFRAG; ni++) {
                uint32_t off = 2u * (unsigned)((wn + ni * 8 + b_row) * PAD + kb + b_col);
                ldm_x2(bh[ni], bH + off);
                ldm_x2(bl[ni], bL + off);
            }
#pragma unroll
            for (int mi = 0; mi < 4; mi++)
#pragma unroll
                for (int ni = 0; ni < NFRAG; ni++) {
                    mma16816(acc[mi][ni], ah[mi], bh[ni]);
                    mma16816(acc[mi][ni], ah[mi], bl[ni]);
                    mma16816(acc[mi][ni], al[mi], bh[ni]);
                }
        }
    };

    constexpr int NITER = DMODEL / BK;
    stage_load(0, 0);
    for (int it = 0; it < NITER; it++) {
        if (it + 1 < NITER) { stage_load((it + 1) & 1, (it + 1) * BK); cp_wait<1>(); }
        else                { cp_wait<0>(); }
        __syncthreads();
        compute(it & 1);
        __syncthreads();
    }

    // ------------------------------- epilogue -------------------------------
#pragma unroll
    for (int mi = 0; mi < 4; mi++)
#pragma unroll
        for (int ni = 0; ni < NFRAG; ni++)
#pragma unroll
            for (int half = 0; half < 2; half++) {
                const int r = m0 + wm + mi * 16 + g + half * 8;
                const int c = n0 + wn + ni * 8 + tk;
                float v0 = acc[mi][ni][half * 2 + 0];
                float v1 = acc[mi][ni][half * 2 + 1];
                if (bias) { v0 += bias[c]; v1 += bias[c + 1]; }

                if (MODE == 0) {
                    float2 o; o.x = v0; o.y = v1;
                    *(float2*)&((float*)Cv)[(size_t)r * DMODEL + c] = o;
                } else if (MODE == 1) {
                    int b = r >> 11, s = r & (SEQ - 1);
                    int h = c >> 6,  d = c & (DH - 1);
                    size_t idx = ((size_t)((b * HEADS + h) * SEQ + s)) * DH + d;
                    unsigned uh, ul; split2pack(v0, v1, uh, ul);
                    *(unsigned*)((bf16*)Cv  + idx) = uh;
                    *(unsigned*)((bf16*)C2v + idx) = ul;
                } else { // MODE 2: [b,h,d,s]
                    int b = r >> 11, s = r & (SEQ - 1);
                    int h = c >> 6,  d = c & (DH - 1);
                    size_t idx = ((size_t)((b * HEADS + h) * DH + d)) * SEQ + s;
                    bf16 h0, l0, h1, l1; split1(v0, h0, l0); split1(v1, h1, l1);
                    ((bf16*)Cv)[idx]        = h0;
                    ((bf16*)Cv)[idx + SEQ]  = h1;
                    ((bf16*)C2v)[idx]       = l0;
                    ((bf16*)C2v)[idx + SEQ] = l1;
                }
            }
}

// ---------------------------------------------------------------------------
// Fused flash attention, 3xbf16 emulation, ldmatrix fragment loads.
// ---------------------------------------------------------------------------
__global__ void __launch_bounds__(256, 1)
flash_attn(const bf16* __restrict__ Qh, const bf16* __restrict__ Ql,
           const bf16* __restrict__ Kh, const bf16* __restrict__ Kl,
           const bf16* __restrict__ Vh, const bf16* __restrict__ Vl,
           bf16* __restrict__ Oh, bf16* __restrict__ Ol)
{
    constexpr int PADK = 72, PADV = 136;
    constexpr int KSTG = 128 * PADK, VSTG = 64 * PADV;
    extern __shared__ bf16 sm[];
    bf16* sKh = sm;
    bf16* sKl = sm + 2 * KSTG;
    bf16* sVh = sm + 4 * KSTG;
    bf16* sVl = sVh + 2 * VSTG;
    const uint32_t usm = (uint32_t)__cvta_generic_to_shared(sm);

    const int z = blockIdx.y;
    const bf16* pQh = Qh + (size_t)z * SEQ * DH;
    const bf16* pQl = Ql + (size_t)z * SEQ * DH;
    const bf16* pKh = Kh + (size_t)z * SEQ * DH;
    const bf16* pKl = Kl + (size_t)z * SEQ * DH;
    const bf16* pVh = Vh + (size_t)z * DH * SEQ;
    const bf16* pVl = Vl + (size_t)z * DH * SEQ;

    const int tid = threadIdx.x;
    const int lane = tid & 31, wid = tid >> 5;
    const int g = lane >> 2, tk = (lane & 3) * 2;
    const int r0 = blockIdx.x * 128 + wid * 16 + g;

    // ldmatrix x4 lane mapping for B-type pair loads (rows 2x8, cols 2x8)
    const int ld_row = ((lane >> 4) & 1) * 8 + (lane & 7);
    const int ld_col = ((lane >> 3) & 1) * 8;

    unsigned aQh[4][4], aQl[4][4];
#pragma unroll
    for (int kk = 0; kk < 4; kk++) {
        int kc = kk * 16 + tk;
        aQh[kk][0] = *(const unsigned*)&pQh[(size_t)r0 * DH + kc];
        aQh[kk][1] = *(const unsigned*)&pQh[(size_t)(r0 + 8) * DH + kc];
        aQh[kk][2] = *(const unsigned*)&pQh[(size_t)r0 * DH + kc + 8];
        aQh[kk][3] = *(const unsigned*)&pQh[(size_t)(r0 + 8) * DH + kc + 8];
        aQl[kk][0] = *(const unsigned*)&pQl[(size_t)r0 * DH + kc];
        aQl[kk][1] = *(const unsigned*)&pQl[(size_t)(r0 + 8) * DH + kc];
        aQl[kk][2] = *(const unsigned*)&pQl[(size_t)r0 * DH + kc + 8];
        aQl[kk][3] = *(const unsigned*)&pQl[(size_t)(r0 + 8) * DH + kc + 8];
    }

    auto stage_load = [&](int s, int kv0) {
#pragma unroll
        for (int c = tid; c < 1024; c += 256) {
            int row = c >> 3, qd = (c & 7) * 8;
            size_t go = (size_t)(kv0 + row) * DH + qd;
            int so = s * KSTG + row * PADK + qd;
            cpasync16(sKh + so, pKh + go);
            cpasync16(sKl + so, pKl + go);
        }
#pragma unroll
        for (int c = tid; c < 1024; c += 256) {
            int d = c >> 4, qd = (c & 15) * 8;
            size_t go = (size_t)d * SEQ + kv0 + qd;
            int so = s * VSTG + d * PADV + qd;
            cpasync16(sVh + so, pVh + go);
            cpasync16(sVl + so, pVl + go);
        }
        cp_commit();
    };

    float m0 = -1e30f, m1 = -1e30f, l0 = 0.f, l1 = 0.f;
    float oacc[8][4];
#pragma unroll
    for (int dn = 0; dn < 8; dn++)
#pragma unroll
        for (int r = 0; r < 4; r++) oacc[dn][r] = 0.f;

    stage_load(0, 0);
    for (int it = 0; it < SEQ / 128; it++) {
        if (it + 1 < SEQ / 128) { stage_load((it + 1) & 1, (it + 1) * 128); cp_wait<1>(); }
        else                    { cp_wait<0>(); }
        __syncthreads();

        const uint32_t uKh = usm + 2u * (unsigned)((it & 1) * KSTG);
        const uint32_t uKl = usm + 2u * (unsigned)(2 * KSTG + (it & 1) * KSTG);
        const uint32_t uVh = usm + 2u * (unsigned)(4 * KSTG + (it & 1) * VSTG);
        const uint32_t uVl = usm + 2u * (unsigned)(4 * KSTG + 2 * VSTG + (it & 1) * VSTG);

        // ---- S = Q @ K^T ----
        float sacc[16][4];
#pragma unroll
        for (int nj = 0; nj < 16; nj++) {
#pragma unroll
            for (int r = 0; r < 4; r++) sacc[nj][r] = 0.f;
        }
#pragma unroll
        for (int p = 0; p < 8; p++) {
            const uint32_t offK = 2u * (unsigned)((p * 16 + ld_row) * PADK + ld_col);
#pragma unroll
            for (int kk = 0; kk < 4; kk++) {
                unsigned bh4[4], bl4[4];
                ldm_x4(bh4, uKh + offK + 2u * (unsigned)(kk * 16));
                ldm_x4(bl4, uKl + offK + 2u * (unsigned)(kk * 16));
                mma16816(sacc[2 * p],     aQh[kk], bh4);
                mma16816(sacc[2 * p],     aQh[kk], bl4);
                mma16816(sacc[2 * p],     aQl[kk], bh4);
                mma16816(sacc[2 * p + 1], aQh[kk], bh4 + 2);
                mma16816(sacc[2 * p + 1], aQh[kk], bl4 + 2);
                mma16816(sacc[2 * p + 1], aQl[kk], bh4 + 2);
            }
        }

        // ---- online softmax (exp2 domain) ----
        float cm0 = -1e30f, cm1 = -1e30f;
#pragma unroll
        for (int nj = 0; nj < 16; nj++) {
            sacc[nj][0] *= SCL2; sacc[nj][1] *= SCL2;
            sacc[nj][2] *= SCL2; sacc[nj][3] *= SCL2;
            cm0 = fmaxf(cm0, fmaxf(sacc[nj][0], sacc[nj][1]));
            cm1 = fmaxf(cm1, fmaxf(sacc[nj][2], sacc[nj][3]));
        }
        cm0 = fmaxf(cm0, __shfl_xor_sync(0xffffffffu, cm0, 1));
        cm0 = fmaxf(cm0, __shfl_xor_sync(0xffffffffu, cm0, 2));
        cm1 = fmaxf(cm1, __shfl_xor_sync(0xffffffffu, cm1, 1));
        cm1 = fmaxf(cm1, __shfl_xor_sync(0xffffffffu, cm1, 2));
        float mn0 = fmaxf(m0, cm0), mn1 = fmaxf(m1, cm1);
        float f0 = ex2(m0 - mn0), f1 = ex2(m1 - mn1);
        m0 = mn0; m1 = mn1;

        float ps0 = 0.f, ps1 = 0.f;
#pragma unroll
        for (int nj = 0; nj < 16; nj++) {
            sacc[nj][0] = ex2(sacc[nj][0] - mn0);
            sacc[nj][1] = ex2(sacc[nj][1] - mn0);
            sacc[nj][2] = ex2(sacc[nj][2] - mn1);
            sacc[nj][3] = ex2(sacc[nj][3] - mn1);
            ps0 += sacc[nj][0] + sacc[nj][1];
            ps1 += sacc[nj][2] + sacc[nj][3];
        }
        ps0 += __shfl_xor_sync(0xffffffffu, ps0, 1);
        ps0 += __shfl_xor_sync(0xffffffffu, ps0, 2);
        ps1 += __shfl_xor_sync(0xffffffffu, ps1, 1);
        ps1 += __shfl_xor_sync(0xffffffffu, ps1, 2);
        l0 = l0 * f0 + ps0;
        l1 = l1 * f1 + ps1;

#pragma unroll
        for (int dn = 0; dn < 8; dn++) {
            oacc[dn][0] *= f0; oacc[dn][1] *= f0;
            oacc[dn][2] *= f1; oacc[dn][3] *= f1;
        }

        // ---- O += P @ V ----
#pragma unroll
        for (int kk = 0; kk < 8; kk++) {
            unsigned ah_[4], al_[4];
            const int t0 = 2 * kk, t1 = 2 * kk + 1;
            split2pack(sacc[t0][0], sacc[t0][1], ah_[0], al_[0]);
            split2pack(sacc[t0][2], sacc[t0][3], ah_[1], al_[1]);
            split2pack(sacc[t1][0], sacc[t1][1], ah_[2], al_[2]);
            split2pack(sacc[t1][2], sacc[t1][3], ah_[3], al_[3]);
#pragma unroll
            for (int dp = 0; dp < 4; dp++) {
                const uint32_t offV =
                    2u * (unsigned)((dp * 16 + ld_row) * PADV + kk * 16 + ld_col);
                unsigned vh4[4], vl4[4];
                ldm_x4(vh4, uVh + offV);
                ldm_x4(vl4, uVl + offV);
                mma16816(oacc[2 * dp],     ah_, vh4);
                mma16816(oacc[2 * dp],     ah_, vl4);
                mma16816(oacc[2 * dp],     al_, vh4);
                mma16816(oacc[2 * dp + 1], ah_, vh4 + 2);
                mma16816(oacc[2 * dp + 1], ah_, vl4 + 2);
                mma16816(oacc[2 * dp + 1], al_, vh4 + 2);
            }
        }
        __syncthreads();
    }

    // ---- epilogue ----
    const float inv0 = 1.f / l0, inv1 = 1.f / l1;
    const int b = z >> 4, h = z & (HEADS - 1);
#pragma unroll
    for (int dn = 0; dn < 8; dn++) {
        const int c = h * DH + dn * 8 + tk;
        size_t i0 = ((size_t)(b * SEQ + r0)) * DMODEL + c;
        size_t i1 = ((size_t)(b * SEQ + r0 + 8)) * DMODEL + c;
        unsigned uh, ul;
        split2pack(oacc[dn][0] * inv0, oacc[dn][1] * inv0, uh, ul);
        *(unsigned*)(Oh + i0) = uh; *(unsigned*)(Ol + i0) = ul;
        split2pack(oacc[dn][2] * inv1, oacc[dn][3] * inv1, uh, ul);
        *(unsigned*)(Oh + i1) = uh; *(unsigned*)(Ol + i1) = ul;
    }
}

// ---------------------------------------------------------------------------
extern "C" void kernel_launch(void* const* d_in, const int* in_sizes, int n_in,
                              void* d_out, int out_size)
{
    const float* v  = (const float*)d_in[0];
    const float* k  = (const float*)d_in[1];
    const float* q  = (const float*)d_in[2];
    const float* wq = (const float*)d_in[3];
    const float* bq = (const float*)d_in[4];
    const float* wk = (const float*)d_in[5];
    const float* bk = (const float*)d_in[6];
    const float* wv = (const float*)d_in[7];
    const float* bv = (const float*)d_in[8];
    const float* wo = (const float*)d_in[9];
    const float* bo = (const float*)d_in[10];
    float* out = (float*)d_out;

    bf16 *q_hi, *q_lo, *k_hi, *k_lo, *v_hi, *v_lo;
    bf16 *wqT_hi, *wqT_lo, *wkT_hi, *wkT_lo, *wvT_hi, *wvT_lo, *woT_hi, *woT_lo;
    bf16 *Qh_hi, *Qh_lo, *Kh_hi, *Kh_lo, *VhT_hi, *VhT_lo, *Att_hi, *Att_lo;
    cudaGetSymbolAddress((void**)&q_hi,  g_q_hi);  cudaGetSymbolAddress((void**)&q_lo,  g_q_lo);
    cudaGetSymbolAddress((void**)&k_hi,  g_k_hi);  cudaGetSymbolAddress((void**)&k_lo,  g_k_lo);
    cudaGetSymbolAddress((void**)&v_hi,  g_v_hi);  cudaGetSymbolAddress((void**)&v_lo,  g_v_lo);
    cudaGetSymbolAddress((void**)&wqT_hi, g_wqT_hi); cudaGetSymbolAddress((void**)&wqT_lo, g_wqT_lo);
    cudaGetSymbolAddress((void**)&wkT_hi, g_wkT_hi); cudaGetSymbolAddress((void**)&wkT_lo, g_wkT_lo);
    cudaGetSymbolAddress((void**)&wvT_hi, g_wvT_hi); cudaGetSymbolAddress((void**)&wvT_lo, g_wvT_lo);
    cudaGetSymbolAddress((void**)&woT_hi, g_woT_hi); cudaGetSymbolAddress((void**)&woT_lo, g_woT_lo);
    cudaGetSymbolAddress((void**)&Qh_hi,  g_Qh_hi);  cudaGetSymbolAddress((void**)&Qh_lo,  g_Qh_lo);
    cudaGetSymbolAddress((void**)&Kh_hi,  g_Kh_hi);  cudaGetSymbolAddress((void**)&Kh_lo,  g_Kh_lo);
    cudaGetSymbolAddress((void**)&VhT_hi, g_VhT_hi); cudaGetSymbolAddress((void**)&VhT_lo, g_VhT_lo);
    cudaGetSymbolAddress((void**)&Att_hi, g_Att_hi); cudaGetSymbolAddress((void**)&Att_lo, g_Att_lo);

    const size_t smemGE = (size_t)(8 * 128 * 40) * sizeof(bf16);                  // 81920
    const size_t smemFA = (size_t)(4 * 128 * 72 + 4 * 64 * 136) * sizeof(bf16);   // 143360
    cudaFuncSetAttribute(gemm3<0>, cudaFuncAttributeMaxDynamicSharedMemorySize, (int)smemGE);
    cudaFuncSetAttribute(gemm3<1>, cudaFuncAttributeMaxDynamicSharedMemorySize, (int)smemGE);
    cudaFuncSetAttribute(gemm3<2>, cudaFuncAttributeMaxDynamicSharedMemorySize, (int)smemGE);
    cudaFuncSetAttribute(flash_attn, cudaFuncAttributeMaxDynamicSharedMemorySize, (int)smemFA);

    // 1) split inputs + transpose/split weights
    split_k<<<1024, 256>>>(q, q_hi, q_lo, NROWS * DMODEL);
    split_k<<<1024, 256>>>(k, k_hi, k_lo, NROWS * DMODEL);
    split_k<<<1024, 256>>>(v, v_hi, v_lo, NROWS * DMODEL);
    {
        dim3 g(32, 32), b(32, 8);
        tsplit_k<<<g, b>>>(wq, wqT_hi, wqT_lo);
        tsplit_k<<<g, b>>>(wk, wkT_hi, wkT_lo);
        tsplit_k<<<g, b>>>(wv, wvT_hi, wvT_lo);
        tsplit_k<<<g, b>>>(wo, woT_hi, woT_lo);
    }

    // 2) QKV projections with head-split epilogues
    {
        dim3 grid(DMODEL / 128, NROWS / 128);
        gemm3<1><<<grid, 256, smemGE>>>(q_hi, q_lo, wqT_hi, wqT_lo, bq, Qh_hi, Qh_lo);
        gemm3<1><<<grid, 256, smemGE>>>(k_hi, k_lo, wkT_hi, wkT_lo, bk, Kh_hi, Kh_lo);
        gemm3<2><<<grid, 256, smemGE>>>(v_hi, v_lo, wvT_hi, wvT_lo, bv, VhT_hi, VhT_lo);
    }

    // 3) fused attention (QK^T -> online softmax -> PV)
    {
        dim3 grid(SEQ / 128, ZBH);
        flash_attn<<<grid, 256, smemFA>>>(Qh_hi, Qh_lo, Kh_hi, Kh_lo,
                                          VhT_hi, VhT_lo, Att_hi, Att_lo);
    }

    // 4) out = Att @ wo + bo (fp32 out)
    {
        dim3 grid(DMODEL / 128, NROWS / 128);
        gemm3<0><<<grid, 256, smemGE>>>(Att_hi, Att_lo, woT_hi, woT_lo, bo, out, nullptr);
    }
}

// round 11
// speedup vs baseline: 3.7223x; 1.0559x over previous
#include <cuda_runtime.h>
#include <cuda_bf16.h>
#include <math.h>
#include <stdint.h>

#define BATCH   2
#define SEQ     2048
#define DMODEL  1024
#define HEADS   16
#define DH      64
#define NROWS   (BATCH * SEQ)            // 4096
#define ZBH     (BATCH * HEADS)          // 32
#define SCALE_QK 0.125f
#define SCL2 0.1803368801111204f         // 0.125 * log2(e)

typedef __nv_bfloat16 bf16;

// ------------------------- device scratch (statics) -------------------------
__device__ bf16 g_q_hi[NROWS * DMODEL], g_q_lo[NROWS * DMODEL];
__device__ bf16 g_k_hi[NROWS * DMODEL], g_k_lo[NROWS * DMODEL];
__device__ bf16 g_v_hi[NROWS * DMODEL], g_v_lo[NROWS * DMODEL];

__device__ bf16 g_wqT_hi[DMODEL * DMODEL], g_wqT_lo[DMODEL * DMODEL];
__device__ bf16 g_wkT_hi[DMODEL * DMODEL], g_wkT_lo[DMODEL * DMODEL];
__device__ bf16 g_wvT_hi[DMODEL * DMODEL], g_wvT_lo[DMODEL * DMODEL];
__device__ bf16 g_woT_hi[DMODEL * DMODEL], g_woT_lo[DMODEL * DMODEL];

__device__ bf16 g_Qh_hi [ZBH * SEQ * DH], g_Qh_lo [ZBH * SEQ * DH];  // [b,h,s,d]
__device__ bf16 g_Kh_hi [ZBH * SEQ * DH], g_Kh_lo [ZBH * SEQ * DH];  // [b,h,s,d]
__device__ bf16 g_VhT_hi[ZBH * DH * SEQ], g_VhT_lo[ZBH * DH * SEQ];  // [b,h,d,s]

__device__ bf16 g_Att_hi[NROWS * DMODEL], g_Att_lo[NROWS * DMODEL];  // [b,s,h*d]

// ------------------------------- helpers ------------------------------------
__device__ __forceinline__ void split1(float x, bf16& h, bf16& l) {
    h = __float2bfloat16_rn(x);
    l = __float2bfloat16_rn(x - __bfloat162float(h));
}
__device__ __forceinline__ void split2pack(float x0, float x1, unsigned& hi, unsigned& lo) {
    bf16 h0, l0, h1, l1;
    split1(x0, h0, l0); split1(x1, h1, l1);
    __nv_bfloat162 th; th.x = h0; th.y = h1;
    __nv_bfloat162 tl; tl.x = l0; tl.y = l1;
    hi = *(unsigned*)&th; lo = *(unsigned*)&tl;
}
__device__ __forceinline__ float ex2(float x) {
    float r;
    asm("ex2.approx.ftz.f32 %0, %1;" : "=f"(r) : "f"(x));
    return r;
}
__device__ __forceinline__ void cpasync16(bf16* dst, const bf16* src) {
    uint32_t d = (uint32_t)__cvta_generic_to_shared(dst);
    asm volatile("cp.async.cg.shared.global [%0], [%1], 16;\n" :: "r"(d), "l"(src));
}
__device__ __forceinline__ void cp_commit() { asm volatile("cp.async.commit_group;\n"); }
template<int N> __device__ __forceinline__ void cp_wait() {
    asm volatile("cp.async.wait_group %0;\n" :: "n"(N));
}
__device__ __forceinline__ void mma16816(float* c, const unsigned* a, const unsigned* b) {
    asm volatile(
        "mma.sync.aligned.m16n8k16.row.col.f32.bf16.bf16.f32 "
        "{%0,%1,%2,%3}, {%4,%5,%6,%7}, {%8,%9}, {%0,%1,%2,%3};"
        : "+f"(c[0]), "+f"(c[1]), "+f"(c[2]), "+f"(c[3])
        : "r"(a[0]), "r"(a[1]), "r"(a[2]), "r"(a[3]), "r"(b[0]), "r"(b[1]));
}
__device__ __forceinline__ void ldm_x4(unsigned* r, uint32_t addr) {
    asm volatile("ldmatrix.sync.aligned.m8n8.x4.shared.b16 {%0,%1,%2,%3}, [%4];"
        : "=r"(r[0]), "=r"(r[1]), "=r"(r[2]), "=r"(r[3]) : "r"(addr));
}
__device__ __forceinline__ void ldm_x2(unsigned* r, uint32_t addr) {
    asm volatile("ldmatrix.sync.aligned.m8n8.x2.shared.b16 {%0,%1}, [%2];"
        : "=r"(r[0]), "=r"(r[1]) : "r"(addr));
}

// ------------------- merged split / transpose kernels -----------------------
// One launch: split q,k,v fp32 -> bf16 hi/lo (blockIdx.y selects tensor)
__global__ void split3_k(const float* __restrict__ q, const float* __restrict__ k,
                         const float* __restrict__ v,
                         bf16* __restrict__ qh, bf16* __restrict__ ql,
                         bf16* __restrict__ kh, bf16* __restrict__ kl,
                         bf16* __restrict__ vh, bf16* __restrict__ vl)
{
    const float* src = (blockIdx.y == 0) ? q : (blockIdx.y == 1) ? k : v;
    bf16* hi = (blockIdx.y == 0) ? qh : (blockIdx.y == 1) ? kh : vh;
    bf16* lo = (blockIdx.y == 0) ? ql : (blockIdx.y == 1) ? kl : vl;
    const int n = NROWS * DMODEL;
    for (int i = blockIdx.x * blockDim.x + threadIdx.x; i < n; i += gridDim.x * blockDim.x) {
        bf16 h, l; split1(src[i], h, l);
        hi[i] = h; lo[i] = l;
    }
}

// One launch: transpose+split all 4 weights (blockIdx.z selects)
__global__ void tsplit4_k(const float* __restrict__ wq, const float* __restrict__ wk,
                          const float* __restrict__ wv, const float* __restrict__ wo,
                          bf16* __restrict__ qh, bf16* __restrict__ ql,
                          bf16* __restrict__ kh, bf16* __restrict__ kl,
                          bf16* __restrict__ vh, bf16* __restrict__ vl,
                          bf16* __restrict__ oh, bf16* __restrict__ ol)
{
    const int zz = blockIdx.z;
    const float* W = (zz == 0) ? wq : (zz == 1) ? wk : (zz == 2) ? wv : wo;
    bf16* hiT = (zz == 0) ? qh : (zz == 1) ? kh : (zz == 2) ? vh : oh;
    bf16* loT = (zz == 0) ? ql : (zz == 1) ? kl : (zz == 2) ? vl : ol;

    __shared__ float t[32][33];
    const int bn = blockIdx.x * 32;
    const int bk = blockIdx.y * 32;
    for (int r = threadIdx.y; r < 32; r += 8)
        t[r][threadIdx.x] = W[(size_t)(bk + r) * DMODEL + bn + threadIdx.x];
    __syncthreads();
    for (int r = threadIdx.y; r < 32; r += 8) {
        float v = t[threadIdx.x][r];
        bf16 h, l; split1(v, h, l);
        size_t idx = (size_t)(bn + r) * DMODEL + bk + threadIdx.x;
        hiT[idx] = h; loT[idx] = l;
    }
}

// ---------------------------------------------------------------------------
// 3xBF16 GEMM (mma.sync + ldmatrix), 2 CTAs/SM:  C = (A@B^T) + bias
//   BM=128, BN=128, BK=32; 256 threads; warp tile 64x32.
//   MODE 0: fp32 C row-major; MODE 1: bf16 hi/lo [b,h,s,d]; MODE 2: [b,h,d,s]
// ---------------------------------------------------------------------------
template<int MODE>
__global__ void __launch_bounds__(256, 2)
gemm3(const bf16* __restrict__ Ah, const bf16* __restrict__ Al,
      const bf16* __restrict__ Bh, const bf16* __restrict__ Bl,
      const float* __restrict__ bias, void* Cv, void* C2v)
{
    constexpr int BM = 128, BN = 128, BK = 32;
    constexpr int PAD = 40;
    constexpr int A_STG = BM * PAD;
    constexpr int B_STG = BN * PAD;
    constexpr int NFRAG = 4;

    extern __shared__ bf16 sm[];
    bf16* sAh = sm;
    bf16* sAl = sm + 2 * A_STG;
    bf16* sBh = sm + 4 * A_STG;
    bf16* sBl = sBh + 2 * B_STG;
    const uint32_t usm = (uint32_t)__cvta_generic_to_shared(sm);

    const int tid = threadIdx.x;
    const int lane = tid & 31, wid = tid >> 5;
    const int m0 = blockIdx.y * BM;
    const int n0 = blockIdx.x * BN;
    const int wm = (wid & 1) * 64;
    const int wn = (wid >> 1) * 32;
    const int g  = lane >> 2;
    const int tk = (lane & 3) * 2;

    const int lq = lane >> 3, li = lane & 7;
    const int a_row = (lq & 1) * 8 + li;
    const int a_col = (lq >> 1) * 8;
    const int b_row = li;
    const int b_col = (lq & 1) * 8;

    float acc[4][NFRAG][4];
#pragma unroll
    for (int mi = 0; mi < 4; mi++)
#pragma unroll
        for (int ni = 0; ni < NFRAG; ni++)
#pragma unroll
            for (int r = 0; r < 4; r++) acc[mi][ni][r] = 0.f;

    auto stage_load = [&](int s, int kt) {
#pragma unroll
        for (int c = tid; c < BM * 4; c += 256) {
            int row = c >> 2, q = c & 3;
            size_t go = (size_t)(m0 + row) * DMODEL + kt + q * 8;
            int so = s * A_STG + row * PAD + q * 8;
            cpasync16(sAh + so, Ah + go);
            cpasync16(sAl + so, Al + go);
        }
#pragma unroll
        for (int c = tid; c < BN * 4; c += 256) {
            int row = c >> 2, q = c & 3;
            size_t go = (size_t)(n0 + row) * DMODEL + kt + q * 8;
            int so = s * B_STG + row * PAD + q * 8;
            cpasync16(sBh + so, Bh + go);
            cpasync16(sBl + so, Bl + go);
        }
        cp_commit();
    };

    // B-frags hoisted, A-frags per-mi: live set ~100 regs -> 2 CTAs/SM
    auto compute = [&](int s) {
        const uint32_t aH = usm + 2u * (unsigned)(s * A_STG);
        const uint32_t aL = usm + 2u * (unsigned)(2 * A_STG + s * A_STG);
        const uint32_t bH = usm + 2u * (unsigned)(4 * A_STG + s * B_STG);
        const uint32_t bL = usm + 2u * (unsigned)(4 * A_STG + 2 * B_STG + s * B_STG);
#pragma unroll
        for (int kh = 0; kh < 2; kh++) {
            const int kb = kh * 16;
            unsigned bh[NFRAG][2], bl[NFRAG][2];
#pragma unroll
            for (int ni = 0; ni < NFRAG; ni++) {
                uint32_t off = 2u * (unsigned)((wn + ni * 8 + b_row) * PAD + kb + b_col);
                ldm_x2(bh[ni], bH + off);
                ldm_x2(bl[ni], bL + off);
            }
#pragma unroll
            for (int mi = 0; mi < 4; mi++) {
                unsigned ah[4], al[4];
                uint32_t off = 2u * (unsigned)((wm + mi * 16 + a_row) * PAD + kb + a_col);
                ldm_x4(ah, aH + off);
                ldm_x4(al, aL + off);
#pragma unroll
                for (int ni = 0; ni < NFRAG; ni++) {
                    mma16816(acc[mi][ni], ah, bh[ni]);
                    mma16816(acc[mi][ni], ah, bl[ni]);
                    mma16816(acc[mi][ni], al, bh[ni]);
                }
            }
        }
    };

    constexpr int NITER = DMODEL / BK;
    stage_load(0, 0);
    for (int it = 0; it < NITER; it++) {
        if (it + 1 < NITER) { stage_load((it + 1) & 1, (it + 1) * BK); cp_wait<1>(); }
        else                { cp_wait<0>(); }
        __syncthreads();
        compute(it & 1);
        __syncthreads();
    }

    // ------------------------------- epilogue -------------------------------
#pragma unroll
    for (int mi = 0; mi < 4; mi++)
#pragma unroll
        for (int ni = 0; ni < NFRAG; ni++)
#pragma unroll
            for (int half = 0; half < 2; half++) {
                const int r = m0 + wm + mi * 16 + g + half * 8;
                const int c = n0 + wn + ni * 8 + tk;
                float v0 = acc[mi][ni][half * 2 + 0];
                float v1 = acc[mi][ni][half * 2 + 1];
                if (bias) { v0 += bias[c]; v1 += bias[c + 1]; }

                if (MODE == 0) {
                    float2 o; o.x = v0; o.y = v1;
                    *(float2*)&((float*)Cv)[(size_t)r * DMODEL + c] = o;
                } else if (MODE == 1) {
                    int b = r >> 11, s = r & (SEQ - 1);
                    int h = c >> 6,  d = c & (DH - 1);
                    size_t idx = ((size_t)((b * HEADS + h) * SEQ + s)) * DH + d;
                    unsigned uh, ul; split2pack(v0, v1, uh, ul);
                    *(unsigned*)((bf16*)Cv  + idx) = uh;
                    *(unsigned*)((bf16*)C2v + idx) = ul;
                } else { // MODE 2: [b,h,d,s]
                    int b = r >> 11, s = r & (SEQ - 1);
                    int h = c >> 6,  d = c & (DH - 1);
                    size_t idx = ((size_t)((b * HEADS + h) * DH + d)) * SEQ + s;
                    bf16 h0, l0, h1, l1; split1(v0, h0, l0); split1(v1, h1, l1);
                    ((bf16*)Cv)[idx]        = h0;
                    ((bf16*)Cv)[idx + SEQ]  = h1;
                    ((bf16*)C2v)[idx]       = l0;
                    ((bf16*)C2v)[idx + SEQ] = l1;
                }
            }
}

// ---------------------------------------------------------------------------
// Fused flash attention, 3xbf16 emulation, ldmatrix fragment loads.
// ---------------------------------------------------------------------------
__global__ void __launch_bounds__(256, 1)
flash_attn(const bf16* __restrict__ Qh, const bf16* __restrict__ Ql,
           const bf16* __restrict__ Kh, const bf16* __restrict__ Kl,
           const bf16* __restrict__ Vh, const bf16* __restrict__ Vl,
           bf16* __restrict__ Oh, bf16* __restrict__ Ol)
{
    constexpr int PADK = 72, PADV = 136;
    constexpr int KSTG = 128 * PADK, VSTG = 64 * PADV;
    extern __shared__ bf16 sm[];
    bf16* sKh = sm;
    bf16* sKl = sm + 2 * KSTG;
    bf16* sVh = sm + 4 * KSTG;
    bf16* sVl = sVh + 2 * VSTG;
    const uint32_t usm = (uint32_t)__cvta_generic_to_shared(sm);

    const int z = blockIdx.y;
    const bf16* pQh = Qh + (size_t)z * SEQ * DH;
    const bf16* pQl = Ql + (size_t)z * SEQ * DH;
    const bf16* pKh = Kh + (size_t)z * SEQ * DH;
    const bf16* pKl = Kl + (size_t)z * SEQ * DH;
    const bf16* pVh = Vh + (size_t)z * DH * SEQ;
    const bf16* pVl = Vl + (size_t)z * DH * SEQ;

    const int tid = threadIdx.x;
    const int lane = tid & 31, wid = tid >> 5;
    const int g = lane >> 2, tk = (lane & 3) * 2;
    const int r0 = blockIdx.x * 128 + wid * 16 + g;

    const int ld_row = ((lane >> 4) & 1) * 8 + (lane & 7);
    const int ld_col = ((lane >> 3) & 1) * 8;

    unsigned aQh[4][4], aQl[4][4];
#pragma unroll
    for (int kk = 0; kk < 4; kk++) {
        int kc = kk * 16 + tk;
        aQh[kk][0] = *(const unsigned*)&pQh[(size_t)r0 * DH + kc];
        aQh[kk][1] = *(const unsigned*)&pQh[(size_t)(r0 + 8) * DH + kc];
        aQh[kk][2] = *(const unsigned*)&pQh[(size_t)r0 * DH + kc + 8];
        aQh[kk][3] = *(const unsigned*)&pQh[(size_t)(r0 + 8) * DH + kc + 8];
        aQl[kk][0] = *(const unsigned*)&pQl[(size_t)r0 * DH + kc];
        aQl[kk][1] = *(const unsigned*)&pQl[(size_t)(r0 + 8) * DH + kc];
        aQl[kk][2] = *(const unsigned*)&pQl[(size_t)r0 * DH + kc + 8];
        aQl[kk][3] = *(const unsigned*)&pQl[(size_t)(r0 + 8) * DH + kc + 8];
    }

    auto stage_load = [&](int s, int kv0) {
#pragma unroll
        for (int c = tid; c < 1024; c += 256) {
            int row = c >> 3, qd = (c & 7) * 8;
            size_t go = (size_t)(kv0 + row) * DH + qd;
            int so = s * KSTG + row * PADK + qd;
            cpasync16(sKh + so, pKh + go);
            cpasync16(sKl + so, pKl + go);
        }
#pragma unroll
        for (int c = tid; c < 1024; c += 256) {
            int d = c >> 4, qd = (c & 15) * 8;
            size_t go = (size_t)d * SEQ + kv0 + qd;
            int so = s * VSTG + d * PADV + qd;
            cpasync16(sVh + so, pVh + go);
            cpasync16(sVl + so, pVl + go);
        }
        cp_commit();
    };

    float m0 = -1e30f, m1 = -1e30f, l0 = 0.f, l1 = 0.f;
    float oacc[8][4];
#pragma unroll
    for (int dn = 0; dn < 8; dn++)
#pragma unroll
        for (int r = 0; r < 4; r++) oacc[dn][r] = 0.f;

    stage_load(0, 0);
    for (int it = 0; it < SEQ / 128; it++) {
        if (it + 1 < SEQ / 128) { stage_load((it + 1) & 1, (it + 1) * 128); cp_wait<1>(); }
        else                    { cp_wait<0>(); }
        __syncthreads();

        const uint32_t uKh = usm + 2u * (unsigned)((it & 1) * KSTG);
        const uint32_t uKl = usm + 2u * (unsigned)(2 * KSTG + (it & 1) * KSTG);
        const uint32_t uVh = usm + 2u * (unsigned)(4 * KSTG + (it & 1) * VSTG);
        const uint32_t uVl = usm + 2u * (unsigned)(4 * KSTG + 2 * VSTG + (it & 1) * VSTG);

        // ---- S = Q @ K^T ----
        float sacc[16][4];
#pragma unroll
        for (int nj = 0; nj < 16; nj++) {
#pragma unroll
            for (int r = 0; r < 4; r++) sacc[nj][r] = 0.f;
        }
#pragma unroll
        for (int p = 0; p < 8; p++) {
            const uint32_t offK = 2u * (unsigned)((p * 16 + ld_row) * PADK + ld_col);
#pragma unroll
            for (int kk = 0; kk < 4; kk++) {
                unsigned bh4[4], bl4[4];
                ldm_x4(bh4, uKh + offK + 2u * (unsigned)(kk * 16));
                ldm_x4(bl4, uKl + offK + 2u * (unsigned)(kk * 16));
                mma16816(sacc[2 * p],     aQh[kk], bh4);
                mma16816(sacc[2 * p],     aQh[kk], bl4);
                mma16816(sacc[2 * p],     aQl[kk], bh4);
                mma16816(sacc[2 * p + 1], aQh[kk], bh4 + 2);
                mma16816(sacc[2 * p + 1], aQh[kk], bl4 + 2);
                mma16816(sacc[2 * p + 1], aQl[kk], bh4 + 2);
            }
        }

        // ---- online softmax (exp2 domain) ----
        float cm0 = -1e30f, cm1 = -1e30f;
#pragma unroll
        for (int nj = 0; nj < 16; nj++) {
            sacc[nj][0] *= SCL2; sacc[nj][1] *= SCL2;
            sacc[nj][2] *= SCL2; sacc[nj][3] *= SCL2;
            cm0 = fmaxf(cm0, fmaxf(sacc[nj][0], sacc[nj][1]));
            cm1 = fmaxf(cm1, fmaxf(sacc[nj][2], sacc[nj][3]));
        }
        cm0 = fmaxf(cm0, __shfl_xor_sync(0xffffffffu, cm0, 1));
        cm0 = fmaxf(cm0, __shfl_xor_sync(0xffffffffu, cm0, 2));
        cm1 = fmaxf(cm1, __shfl_xor_sync(0xffffffffu, cm1, 1));
        cm1 = fmaxf(cm1, __shfl_xor_sync(0xffffffffu, cm1, 2));
        float mn0 = fmaxf(m0, cm0), mn1 = fmaxf(m1, cm1);
        float f0 = ex2(m0 - mn0), f1 = ex2(m1 - mn1);
        m0 = mn0; m1 = mn1;

        float ps0 = 0.f, ps1 = 0.f;
#pragma unroll
        for (int nj = 0; nj < 16; nj++) {
            sacc[nj][0] = ex2(sacc[nj][0] - mn0);
            sacc[nj][1] = ex2(sacc[nj][1] - mn0);
            sacc[nj][2] = ex2(sacc[nj][2] - mn1);
            sacc[nj][3] = ex2(sacc[nj][3] - mn1);
            ps0 += sacc[nj][0] + sacc[nj][1];
            ps1 += sacc[nj][2] + sacc[nj][3];
        }
        ps0 += __shfl_xor_sync(0xffffffffu, ps0, 1);
        ps0 += __shfl_xor_sync(0xffffffffu, ps0, 2);
        ps1 += __shfl_xor_sync(0xffffffffu, ps1, 1);
        ps1 += __shfl_xor_sync(0xffffffffu, ps1, 2);
        l0 = l0 * f0 + ps0;
        l1 = l1 * f1 + ps1;

#pragma unroll
        for (int dn = 0; dn < 8; dn++) {
            oacc[dn][0] *= f0; oacc[dn][1] *= f0;
            oacc[dn][2] *= f1; oacc[dn][3] *= f1;
        }

        // ---- O += P @ V ----
#pragma unroll
        for (int kk = 0; kk < 8; kk++) {
            unsigned ah_[4], al_[4];
            const int t0 = 2 * kk, t1 = 2 * kk + 1;
            split2pack(sacc[t0][0], sacc[t0][1], ah_[0], al_[0]);
            split2pack(sacc[t0][2], sacc[t0][3], ah_[1], al_[1]);
            split2pack(sacc[t1][0], sacc[t1][1], ah_[2], al_[2]);
            split2pack(sacc[t1][2], sacc[t1][3], ah_[3], al_[3]);
#pragma unroll
            for (int dp = 0; dp < 4; dp++) {
                const uint32_t offV =
                    2u * (unsigned)((dp * 16 + ld_row) * PADV + kk * 16 + ld_col);
                unsigned vh4[4], vl4[4];
                ldm_x4(vh4, uVh + offV);
                ldm_x4(vl4, uVl + offV);
                mma16816(oacc[2 * dp],     ah_, vh4);
                mma16816(oacc[2 * dp],     ah_, vl4);
                mma16816(oacc[2 * dp],     al_, vh4);
                mma16816(oacc[2 * dp + 1], ah_, vh4 + 2);
                mma16816(oacc[2 * dp + 1], ah_, vl4 + 2);
                mma16816(oacc[2 * dp + 1], al_, vh4 + 2);
            }
        }
        __syncthreads();
    }

    // ---- epilogue ----
    const float inv0 = 1.f / l0, inv1 = 1.f / l1;
    const int b = z >> 4, h = z & (HEADS - 1);
#pragma unroll
    for (int dn = 0; dn < 8; dn++) {
        const int c = h * DH + dn * 8 + tk;
        size_t i0 = ((size_t)(b * SEQ + r0)) * DMODEL + c;
        size_t i1 = ((size_t)(b * SEQ + r0 + 8)) * DMODEL + c;
        unsigned uh, ul;
        split2pack(oacc[dn][0] * inv0, oacc[dn][1] * inv0, uh, ul);
        *(unsigned*)(Oh + i0) = uh; *(unsigned*)(Ol + i0) = ul;
        split2pack(oacc[dn][2] * inv1, oacc[dn][3] * inv1, uh, ul);
        *(unsigned*)(Oh + i1) = uh; *(unsigned*)(Ol + i1) = ul;
    }
}

// ---------------------------------------------------------------------------
extern "C" void kernel_launch(void* const* d_in, const int* in_sizes, int n_in,
                              void* d_out, int out_size)
{
    const float* v  = (const float*)d_in[0];
    const float* k  = (const float*)d_in[1];
    const float* q  = (const float*)d_in[2];
    const float* wq = (const float*)d_in[3];
    const float* bq = (const float*)d_in[4];
    const float* wk = (const float*)d_in[5];
    const float* bk = (const float*)d_in[6];
    const float* wv = (const float*)d_in[7];
    const float* bv = (const float*)d_in[8];
    const float* wo = (const float*)d_in[9];
    const float* bo = (const float*)d_in[10];
    float* out = (float*)d_out;

    bf16 *q_hi, *q_lo, *k_hi, *k_lo, *v_hi, *v_lo;
    bf16 *wqT_hi, *wqT_lo, *wkT_hi, *wkT_lo, *wvT_hi, *wvT_lo, *woT_hi, *woT_lo;
    bf16 *Qh_hi, *Qh_lo, *Kh_hi, *Kh_lo, *VhT_hi, *VhT_lo, *Att_hi, *Att_lo;
    cudaGetSymbolAddress((void**)&q_hi,  g_q_hi);  cudaGetSymbolAddress((void**)&q_lo,  g_q_lo);
    cudaGetSymbolAddress((void**)&k_hi,  g_k_hi);  cudaGetSymbolAddress((void**)&k_lo,  g_k_lo);
    cudaGetSymbolAddress((void**)&v_hi,  g_v_hi);  cudaGetSymbolAddress((void**)&v_lo,  g_v_lo);
    cudaGetSymbolAddress((void**)&wqT_hi, g_wqT_hi); cudaGetSymbolAddress((void**)&wqT_lo, g_wqT_lo);
    cudaGetSymbolAddress((void**)&wkT_hi, g_wkT_hi); cudaGetSymbolAddress((void**)&wkT_lo, g_wkT_lo);
    cudaGetSymbolAddress((void**)&wvT_hi, g_wvT_hi); cudaGetSymbolAddress((void**)&wvT_lo, g_wvT_lo);
    cudaGetSymbolAddress((void**)&woT_hi, g_woT_hi); cudaGetSymbolAddress((void**)&woT_lo, g_woT_lo);
    cudaGetSymbolAddress((void**)&Qh_hi,  g_Qh_hi);  cudaGetSymbolAddress((void**)&Qh_lo,  g_Qh_lo);
    cudaGetSymbolAddress((void**)&Kh_hi,  g_Kh_hi);  cudaGetSymbolAddress((void**)&Kh_lo,  g_Kh_lo);
    cudaGetSymbolAddress((void**)&VhT_hi, g_VhT_hi); cudaGetSymbolAddress((void**)&VhT_lo, g_VhT_lo);
    cudaGetSymbolAddress((void**)&Att_hi, g_Att_hi); cudaGetSymbolAddress((void**)&Att_lo, g_Att_lo);

    const size_t smemGE = (size_t)(8 * 128 * 40) * sizeof(bf16);                  // 81920
    const size_t smemFA = (size_t)(4 * 128 * 72 + 4 * 64 * 136) * sizeof(bf16);   // 143360
    cudaFuncSetAttribute(gemm3<0>, cudaFuncAttributeMaxDynamicSharedMemorySize, (int)smemGE);
    cudaFuncSetAttribute(gemm3<1>, cudaFuncAttributeMaxDynamicSharedMemorySize, (int)smemGE);
    cudaFuncSetAttribute(gemm3<2>, cudaFuncAttributeMaxDynamicSharedMemorySize, (int)smemGE);
    cudaFuncSetAttribute(flash_attn, cudaFuncAttributeMaxDynamicSharedMemorySize, (int)smemFA);

    // launch 0: split q,k,v   launch 1: transpose+split weights
    {
        dim3 g(512, 3);
        split3_k<<<g, 256>>>(q, k, v, q_hi, q_lo, k_hi, k_lo, v_hi, v_lo);
    }
    {
        dim3 g(32, 32, 4), b(32, 8);
        tsplit4_k<<<g, b>>>(wq, wk, wv, wo,
                            wqT_hi, wqT_lo, wkT_hi, wkT_lo,
                            wvT_hi, wvT_lo, woT_hi, woT_lo);
    }

    // launches 2-4: QKV projections (2 CTAs/SM)
    {
        dim3 grid(DMODEL / 128, NROWS / 128);
        gemm3<1><<<grid, 256, smemGE>>>(q_hi, q_lo, wqT_hi, wqT_lo, bq, Qh_hi, Qh_lo);
        gemm3<1><<<grid, 256, smemGE>>>(k_hi, k_lo, wkT_hi, wkT_lo, bk, Kh_hi, Kh_lo);
        gemm3<2><<<grid, 256, smemGE>>>(v_hi, v_lo, wvT_hi, wvT_lo, bv, VhT_hi, VhT_lo);
    }

    // launch 5 (ncu capture target): fused attention
    {
        dim3 grid(SEQ / 128, ZBH);
        flash_attn<<<grid, 256, smemFA>>>(Qh_hi, Qh_lo, Kh_hi, Kh_lo,
                                          VhT_hi, VhT_lo, Att_hi, Att_lo);
    }

    // launch 6: out = Att @ wo + bo (fp32 out)
    {
        dim3 grid(DMODEL / 128, NROWS / 128);
        gemm3<0><<<grid, 256, smemGE>>>(Att_hi, Att_lo, woT_hi, woT_lo, bo, out, nullptr);
    }
}

// round 12
// speedup vs baseline: 3.8919x; 1.0456x over previous
#include <cuda_runtime.h>
#include <cuda_bf16.h>
#include <math.h>
#include <stdint.h>

#define BATCH   2
#define SEQ     2048
#define DMODEL  1024
#define HEADS   16
#define DH      64
#define NROWS   (BATCH * SEQ)            // 4096
#define ZBH     (BATCH * HEADS)          // 32
#define SCL2 0.1803368801111204f         // 0.125 * log2(e)

typedef __nv_bfloat16 bf16;

// ------------------------- device scratch (statics) -------------------------
__device__ bf16 g_q_hi[NROWS * DMODEL], g_q_lo[NROWS * DMODEL];
__device__ bf16 g_k_hi[NROWS * DMODEL], g_k_lo[NROWS * DMODEL];
__device__ bf16 g_v_hi[NROWS * DMODEL], g_v_lo[NROWS * DMODEL];

__device__ bf16 g_wqT_hi[DMODEL * DMODEL], g_wqT_lo[DMODEL * DMODEL];
__device__ bf16 g_wkT_hi[DMODEL * DMODEL], g_wkT_lo[DMODEL * DMODEL];
__device__ bf16 g_wvT_hi[DMODEL * DMODEL], g_wvT_lo[DMODEL * DMODEL];
__device__ bf16 g_woT_hi[DMODEL * DMODEL], g_woT_lo[DMODEL * DMODEL];

__device__ bf16 g_Qh_hi [ZBH * SEQ * DH], g_Qh_lo [ZBH * SEQ * DH];  // [b,h,s,d]
__device__ bf16 g_Kh_hi [ZBH * SEQ * DH], g_Kh_lo [ZBH * SEQ * DH];  // [b,h,s,d]
__device__ bf16 g_VhT_hi[ZBH * DH * SEQ], g_VhT_lo[ZBH * DH * SEQ];  // [b,h,d,s]

__device__ bf16 g_Att_hi[NROWS * DMODEL], g_Att_lo[NROWS * DMODEL];  // [b,s,h*d]

// ------------------------------- helpers ------------------------------------
__device__ __forceinline__ void split1(float x, bf16& h, bf16& l) {
    h = __float2bfloat16_rn(x);
    l = __float2bfloat16_rn(x - __bfloat162float(h));
}
__device__ __forceinline__ void split2pack(float x0, float x1, unsigned& hi, unsigned& lo) {
    bf16 h0, l0, h1, l1;
    split1(x0, h0, l0); split1(x1, h1, l1);
    __nv_bfloat162 th; th.x = h0; th.y = h1;
    __nv_bfloat162 tl; tl.x = l0; tl.y = l1;
    hi = *(unsigned*)&th; lo = *(unsigned*)&tl;
}
__device__ __forceinline__ float ex2(float x) {
    float r;
    asm("ex2.approx.ftz.f32 %0, %1;" : "=f"(r) : "f"(x));
    return r;
}
__device__ __forceinline__ void cpasync16(bf16* dst, const bf16* src) {
    uint32_t d = (uint32_t)__cvta_generic_to_shared(dst);
    asm volatile("cp.async.cg.shared.global [%0], [%1], 16;\n" :: "r"(d), "l"(src));
}
__device__ __forceinline__ void cp_commit() { asm volatile("cp.async.commit_group;\n"); }
template<int N> __device__ __forceinline__ void cp_wait() {
    asm volatile("cp.async.wait_group %0;\n" :: "n"(N));
}
__device__ __forceinline__ void mma16816(float* c, const unsigned* a, const unsigned* b) {
    asm volatile(
        "mma.sync.aligned.m16n8k16.row.col.f32.bf16.bf16.f32 "
        "{%0,%1,%2,%3}, {%4,%5,%6,%7}, {%8,%9}, {%0,%1,%2,%3};"
        : "+f"(c[0]), "+f"(c[1]), "+f"(c[2]), "+f"(c[3])
        : "r"(a[0]), "r"(a[1]), "r"(a[2]), "r"(a[3]), "r"(b[0]), "r"(b[1]));
}
__device__ __forceinline__ void ldm_x4(unsigned* r, uint32_t addr) {
    asm volatile("ldmatrix.sync.aligned.m8n8.x4.shared.b16 {%0,%1,%2,%3}, [%4];"
        : "=r"(r[0]), "=r"(r[1]), "=r"(r[2]), "=r"(r[3]) : "r"(addr));
}
__device__ __forceinline__ void ldm_x2(unsigned* r, uint32_t addr) {
    asm volatile("ldmatrix.sync.aligned.m8n8.x2.shared.b16 {%0,%1}, [%2];"
        : "=r"(r[0]), "=r"(r[1]) : "r"(addr));
}

// ------------------- merged split / transpose kernels -----------------------
__global__ void split3_k(const float* __restrict__ q, const float* __restrict__ k,
                         const float* __restrict__ v,
                         bf16* __restrict__ qh, bf16* __restrict__ ql,
                         bf16* __restrict__ kh, bf16* __restrict__ kl,
                         bf16* __restrict__ vh, bf16* __restrict__ vl)
{
    const float* src = (blockIdx.y == 0) ? q : (blockIdx.y == 1) ? k : v;
    bf16* hi = (blockIdx.y == 0) ? qh : (blockIdx.y == 1) ? kh : vh;
    bf16* lo = (blockIdx.y == 0) ? ql : (blockIdx.y == 1) ? kl : vl;
    const int n = NROWS * DMODEL;
    for (int i = blockIdx.x * blockDim.x + threadIdx.x; i < n; i += gridDim.x * blockDim.x) {
        bf16 h, l; split1(src[i], h, l);
        hi[i] = h; lo[i] = l;
    }
}

__global__ void tsplit4_k(const float* __restrict__ wq, const float* __restrict__ wk,
                          const float* __restrict__ wv, const float* __restrict__ wo,
                          bf16* __restrict__ qh, bf16* __restrict__ ql,
                          bf16* __restrict__ kh, bf16* __restrict__ kl,
                          bf16* __restrict__ vh, bf16* __restrict__ vl,
                          bf16* __restrict__ oh, bf16* __restrict__ ol)
{
    const int zz = blockIdx.z;
    const float* W = (zz == 0) ? wq : (zz == 1) ? wk : (zz == 2) ? wv : wo;
    bf16* hiT = (zz == 0) ? qh : (zz == 1) ? kh : (zz == 2) ? vh : oh;
    bf16* loT = (zz == 0) ? ql : (zz == 1) ? kl : (zz == 2) ? vl : ol;

    __shared__ float t[32][33];
    const int bn = blockIdx.x * 32;
    const int bk = blockIdx.y * 32;
    for (int r = threadIdx.y; r < 32; r += 8)
        t[r][threadIdx.x] = W[(size_t)(bk + r) * DMODEL + bn + threadIdx.x];
    __syncthreads();
    for (int r = threadIdx.y; r < 32; r += 8) {
        float v = t[threadIdx.x][r];
        bf16 h, l; split1(v, h, l);
        size_t idx = (size_t)(bn + r) * DMODEL + bk + threadIdx.x;
        hiT[idx] = h; loT[idx] = l;
    }
}

// ---------------------------------------------------------------------------
// 3xBF16 GEMM core (mma.sync + ldmatrix), shared by QKV-batched and out-proj.
//   mode: 0 = fp32 C row-major; 1 = bf16 hi/lo [b,h,s,d]; 2 = bf16 hi/lo [b,h,d,s]
// ---------------------------------------------------------------------------
__device__ __forceinline__ void gemm3_body(
    const bf16* __restrict__ Ah, const bf16* __restrict__ Al,
    const bf16* __restrict__ Bh, const bf16* __restrict__ Bl,
    const float* __restrict__ bias, void* Cv, void* C2v, int mode)
{
    constexpr int BM = 128, BN = 128, BK = 32;
    constexpr int PAD = 40;
    constexpr int A_STG = BM * PAD;
    constexpr int B_STG = BN * PAD;
    constexpr int NFRAG = 4;

    extern __shared__ bf16 sm[];
    bf16* sAh = sm;
    bf16* sAl = sm + 2 * A_STG;
    bf16* sBh = sm + 4 * A_STG;
    bf16* sBl = sBh + 2 * B_STG;
    const uint32_t usm = (uint32_t)__cvta_generic_to_shared(sm);

    const int tid = threadIdx.x;
    const int lane = tid & 31, wid = tid >> 5;
    const int m0 = blockIdx.y * BM;
    const int n0 = blockIdx.x * BN;
    const int wm = (wid & 1) * 64;
    const int wn = (wid >> 1) * 32;
    const int g  = lane >> 2;
    const int tk = (lane & 3) * 2;

    const int lq = lane >> 3, li = lane & 7;
    const int a_row = (lq & 1) * 8 + li;
    const int a_col = (lq >> 1) * 8;
    const int b_row = li;
    const int b_col = (lq & 1) * 8;

    float acc[4][NFRAG][4];
#pragma unroll
    for (int mi = 0; mi < 4; mi++)
#pragma unroll
        for (int ni = 0; ni < NFRAG; ni++)
#pragma unroll
            for (int r = 0; r < 4; r++) acc[mi][ni][r] = 0.f;

    auto stage_load = [&](int s, int kt) {
#pragma unroll
        for (int c = tid; c < BM * 4; c += 256) {
            int row = c >> 2, q = c & 3;
            size_t go = (size_t)(m0 + row) * DMODEL + kt + q * 8;
            int so = s * A_STG + row * PAD + q * 8;
            cpasync16(sAh + so, Ah + go);
            cpasync16(sAl + so, Al + go);
        }
#pragma unroll
        for (int c = tid; c < BN * 4; c += 256) {
            int row = c >> 2, q = c & 3;
            size_t go = (size_t)(n0 + row) * DMODEL + kt + q * 8;
            int so = s * B_STG + row * PAD + q * 8;
            cpasync16(sBh + so, Bh + go);
            cpasync16(sBl + so, Bl + go);
        }
        cp_commit();
    };

    auto compute = [&](int s) {
        const uint32_t aH = usm + 2u * (unsigned)(s * A_STG);
        const uint32_t aL = usm + 2u * (unsigned)(2 * A_STG + s * A_STG);
        const uint32_t bH = usm + 2u * (unsigned)(4 * A_STG + s * B_STG);
        const uint32_t bL = usm + 2u * (unsigned)(4 * A_STG + 2 * B_STG + s * B_STG);
#pragma unroll
        for (int kh = 0; kh < 2; kh++) {
            const int kb = kh * 16;
            unsigned bh[NFRAG][2], bl[NFRAG][2];
#pragma unroll
            for (int ni = 0; ni < NFRAG; ni++) {
                uint32_t off = 2u * (unsigned)((wn + ni * 8 + b_row) * PAD + kb + b_col);
                ldm_x2(bh[ni], bH + off);
                ldm_x2(bl[ni], bL + off);
            }
#pragma unroll
            for (int mi = 0; mi < 4; mi++) {
                unsigned ah[4], al[4];
                uint32_t off = 2u * (unsigned)((wm + mi * 16 + a_row) * PAD + kb + a_col);
                ldm_x4(ah, aH + off);
                ldm_x4(al, aL + off);
#pragma unroll
                for (int ni = 0; ni < NFRAG; ni++) {
                    mma16816(acc[mi][ni], ah, bh[ni]);
                    mma16816(acc[mi][ni], ah, bl[ni]);
                    mma16816(acc[mi][ni], al, bh[ni]);
                }
            }
        }
    };

    constexpr int NITER = DMODEL / BK;
    stage_load(0, 0);
    for (int it = 0; it < NITER; it++) {
        if (it + 1 < NITER) { stage_load((it + 1) & 1, (it + 1) * BK); cp_wait<1>(); }
        else                { cp_wait<0>(); }
        __syncthreads();
        compute(it & 1);
        __syncthreads();
    }

#pragma unroll
    for (int mi = 0; mi < 4; mi++)
#pragma unroll
        for (int ni = 0; ni < NFRAG; ni++)
#pragma unroll
            for (int half = 0; half < 2; half++) {
                const int r = m0 + wm + mi * 16 + g + half * 8;
                const int c = n0 + wn + ni * 8 + tk;
                float v0 = acc[mi][ni][half * 2 + 0];
                float v1 = acc[mi][ni][half * 2 + 1];
                if (bias) { v0 += bias[c]; v1 += bias[c + 1]; }

                if (mode == 0) {
                    float2 o; o.x = v0; o.y = v1;
                    *(float2*)&((float*)Cv)[(size_t)r * DMODEL + c] = o;
                } else if (mode == 1) {
                    int b = r >> 11, s = r & (SEQ - 1);
                    int h = c >> 6,  d = c & (DH - 1);
                    size_t idx = ((size_t)((b * HEADS + h) * SEQ + s)) * DH + d;
                    unsigned uh, ul; split2pack(v0, v1, uh, ul);
                    *(unsigned*)((bf16*)Cv  + idx) = uh;
                    *(unsigned*)((bf16*)C2v + idx) = ul;
                } else { // mode 2: [b,h,d,s]
                    int b = r >> 11, s = r & (SEQ - 1);
                    int h = c >> 6,  d = c & (DH - 1);
                    size_t idx = ((size_t)((b * HEADS + h) * DH + d)) * SEQ + s;
                    bf16 h0, l0, h1, l1; split1(v0, h0, l0); split1(v1, h1, l1);
                    ((bf16*)Cv)[idx]        = h0;
                    ((bf16*)Cv)[idx + SEQ]  = h1;
                    ((bf16*)C2v)[idx]       = l0;
                    ((bf16*)C2v)[idx + SEQ] = l1;
                }
            }
}

// One launch for all three QKV projections: blockIdx.z selects (A, W, bias, out).
__global__ void __launch_bounds__(256, 2)
gemm3_qkv(const bf16* __restrict__ qh, const bf16* __restrict__ ql,
          const bf16* __restrict__ kh, const bf16* __restrict__ kl,
          const bf16* __restrict__ vh, const bf16* __restrict__ vl,
          const bf16* __restrict__ wqh, const bf16* __restrict__ wql,
          const bf16* __restrict__ wkh, const bf16* __restrict__ wkl,
          const bf16* __restrict__ wvh, const bf16* __restrict__ wvl,
          const float* __restrict__ bq, const float* __restrict__ bk,
          const float* __restrict__ bv,
          bf16* Qh, bf16* Ql, bf16* Kh, bf16* Kl, bf16* Vh, bf16* Vl)
{
    const int z = blockIdx.z;
    const bf16* Ah = (z == 0) ? qh : (z == 1) ? kh : vh;
    const bf16* Al = (z == 0) ? ql : (z == 1) ? kl : vl;
    const bf16* Bh = (z == 0) ? wqh : (z == 1) ? wkh : wvh;
    const bf16* Bl = (z == 0) ? wql : (z == 1) ? wkl : wvl;
    const float* bias = (z == 0) ? bq : (z == 1) ? bk : bv;
    bf16* Ch  = (z == 0) ? Qh : (z == 1) ? Kh : Vh;
    bf16* C2h = (z == 0) ? Ql : (z == 1) ? Kl : Vl;
    gemm3_body(Ah, Al, Bh, Bl, bias, Ch, C2h, (z == 2) ? 2 : 1);
}

// Output projection: fp32 C
__global__ void __launch_bounds__(256, 2)
gemm3_out(const bf16* __restrict__ Ah, const bf16* __restrict__ Al,
          const bf16* __restrict__ Bh, const bf16* __restrict__ Bl,
          const float* __restrict__ bias, float* Cv)
{
    gemm3_body(Ah, Al, Bh, Bl, bias, Cv, nullptr, 0);
}

// ---------------------------------------------------------------------------
// Fused flash attention, 3xbf16, 64-key chunks, 2 CTAs/SM.
// ---------------------------------------------------------------------------
__global__ void __launch_bounds__(256, 2)
flash_attn(const bf16* __restrict__ Qh, const bf16* __restrict__ Ql,
           const bf16* __restrict__ Kh, const bf16* __restrict__ Kl,
           const bf16* __restrict__ Vh, const bf16* __restrict__ Vl,
           bf16* __restrict__ Oh, bf16* __restrict__ Ol)
{
    constexpr int KC = 64;                 // keys per chunk
    constexpr int PADK = 72, PADV = 72;
    constexpr int KSTG = KC * PADK, VSTG = 64 * PADV;
    extern __shared__ bf16 sm[];
    bf16* sKh = sm;                        // [2][KSTG]
    bf16* sKl = sm + 2 * KSTG;
    bf16* sVh = sm + 4 * KSTG;             // [2][VSTG]
    bf16* sVl = sVh + 2 * VSTG;
    const uint32_t usm = (uint32_t)__cvta_generic_to_shared(sm);

    const int z = blockIdx.y;
    const bf16* pQh = Qh + (size_t)z * SEQ * DH;
    const bf16* pQl = Ql + (size_t)z * SEQ * DH;
    const bf16* pKh = Kh + (size_t)z * SEQ * DH;
    const bf16* pKl = Kl + (size_t)z * SEQ * DH;
    const bf16* pVh = Vh + (size_t)z * DH * SEQ;
    const bf16* pVl = Vl + (size_t)z * DH * SEQ;

    const int tid = threadIdx.x;
    const int lane = tid & 31, wid = tid >> 5;
    const int g = lane >> 2, tk = (lane & 3) * 2;
    const int r0 = blockIdx.x * 128 + wid * 16 + g;

    const int ld_row = ((lane >> 4) & 1) * 8 + (lane & 7);
    const int ld_col = ((lane >> 3) & 1) * 8;

    unsigned aQh[4][4], aQl[4][4];
#pragma unroll
    for (int kk = 0; kk < 4; kk++) {
        int kc = kk * 16 + tk;
        aQh[kk][0] = *(const unsigned*)&pQh[(size_t)r0 * DH + kc];
        aQh[kk][1] = *(const unsigned*)&pQh[(size_t)(r0 + 8) * DH + kc];
        aQh[kk][2] = *(const unsigned*)&pQh[(size_t)r0 * DH + kc + 8];
        aQh[kk][3] = *(const unsigned*)&pQh[(size_t)(r0 + 8) * DH + kc + 8];
        aQl[kk][0] = *(const unsigned*)&pQl[(size_t)r0 * DH + kc];
        aQl[kk][1] = *(const unsigned*)&pQl[(size_t)(r0 + 8) * DH + kc];
        aQl[kk][2] = *(const unsigned*)&pQl[(size_t)r0 * DH + kc + 8];
        aQl[kk][3] = *(const unsigned*)&pQl[(size_t)(r0 + 8) * DH + kc + 8];
    }

    auto stage_load = [&](int s, int kv0) {
#pragma unroll
        for (int c = tid; c < KC * 8; c += 256) {       // K: 64 rows x 64 d
            int row = c >> 3, qd = (c & 7) * 8;
            size_t go = (size_t)(kv0 + row) * DH + qd;
            int so = s * KSTG + row * PADK + qd;
            cpasync16(sKh + so, pKh + go);
            cpasync16(sKl + so, pKl + go);
        }
#pragma unroll
        for (int c = tid; c < 64 * 8; c += 256) {       // V: 64 d x 64 keys
            int d = c >> 3, qd = (c & 7) * 8;
            size_t go = (size_t)d * SEQ + kv0 + qd;
            int so = s * VSTG + d * PADV + qd;
            cpasync16(sVh + so, pVh + go);
            cpasync16(sVl + so, pVl + go);
        }
        cp_commit();
    };

    float m0 = -1e30f, m1 = -1e30f, l0 = 0.f, l1 = 0.f;
    float oacc[8][4];
#pragma unroll
    for (int dn = 0; dn < 8; dn++)
#pragma unroll
        for (int r = 0; r < 4; r++) oacc[dn][r] = 0.f;

    stage_load(0, 0);
    for (int it = 0; it < SEQ / KC; it++) {
        if (it + 1 < SEQ / KC) { stage_load((it + 1) & 1, (it + 1) * KC); cp_wait<1>(); }
        else                   { cp_wait<0>(); }
        __syncthreads();

        const uint32_t uKh = usm + 2u * (unsigned)((it & 1) * KSTG);
        const uint32_t uKl = usm + 2u * (unsigned)(2 * KSTG + (it & 1) * KSTG);
        const uint32_t uVh = usm + 2u * (unsigned)(4 * KSTG + (it & 1) * VSTG);
        const uint32_t uVl = usm + 2u * (unsigned)(4 * KSTG + 2 * VSTG + (it & 1) * VSTG);

        // ---- S = Q @ K^T (16 rows x 64 keys) ----
        float sacc[8][4];
#pragma unroll
        for (int nj = 0; nj < 8; nj++) {
#pragma unroll
            for (int r = 0; r < 4; r++) sacc[nj][r] = 0.f;
        }
#pragma unroll
        for (int p = 0; p < 4; p++) {
            const uint32_t offK = 2u * (unsigned)((p * 16 + ld_row) * PADK + ld_col);
#pragma unroll
            for (int kk = 0; kk < 4; kk++) {
                unsigned bh4[4], bl4[4];
                ldm_x4(bh4, uKh + offK + 2u * (unsigned)(kk * 16));
                ldm_x4(bl4, uKl + offK + 2u * (unsigned)(kk * 16));
                mma16816(sacc[2 * p],     aQh[kk], bh4);
                mma16816(sacc[2 * p],     aQh[kk], bl4);
                mma16816(sacc[2 * p],     aQl[kk], bh4);
                mma16816(sacc[2 * p + 1], aQh[kk], bh4 + 2);
                mma16816(sacc[2 * p + 1], aQh[kk], bl4 + 2);
                mma16816(sacc[2 * p + 1], aQl[kk], bh4 + 2);
            }
        }

        // ---- online softmax (exp2 domain) ----
        float cm0 = -1e30f, cm1 = -1e30f;
#pragma unroll
        for (int nj = 0; nj < 8; nj++) {
            sacc[nj][0] *= SCL2; sacc[nj][1] *= SCL2;
            sacc[nj][2] *= SCL2; sacc[nj][3] *= SCL2;
            cm0 = fmaxf(cm0, fmaxf(sacc[nj][0], sacc[nj][1]));
            cm1 = fmaxf(cm1, fmaxf(sacc[nj][2], sacc[nj][3]));
        }
        cm0 = fmaxf(cm0, __shfl_xor_sync(0xffffffffu, cm0, 1));
        cm0 = fmaxf(cm0, __shfl_xor_sync(0xffffffffu, cm0, 2));
        cm1 = fmaxf(cm1, __shfl_xor_sync(0xffffffffu, cm1, 1));
        cm1 = fmaxf(cm1, __shfl_xor_sync(0xffffffffu, cm1, 2));
        float mn0 = fmaxf(m0, cm0), mn1 = fmaxf(m1, cm1);
        float f0 = ex2(m0 - mn0), f1 = ex2(m1 - mn1);
        m0 = mn0; m1 = mn1;

        float ps0 = 0.f, ps1 = 0.f;
#pragma unroll
        for (int nj = 0; nj < 8; nj++) {
            sacc[nj][0] = ex2(sacc[nj][0] - mn0);
            sacc[nj][1] = ex2(sacc[nj][1] - mn0);
            sacc[nj][2] = ex2(sacc[nj][2] - mn1);
            sacc[nj][3] = ex2(sacc[nj][3] - mn1);
            ps0 += sacc[nj][0] + sacc[nj][1];
            ps1 += sacc[nj][2] + sacc[nj][3];
        }
        ps0 += __shfl_xor_sync(0xffffffffu, ps0, 1);
        ps0 += __shfl_xor_sync(0xffffffffu, ps0, 2);
        ps1 += __shfl_xor_sync(0xffffffffu, ps1, 1);
        ps1 += __shfl_xor_sync(0xffffffffu, ps1, 2);
        l0 = l0 * f0 + ps0;
        l1 = l1 * f1 + ps1;

#pragma unroll
        for (int dn = 0; dn < 8; dn++) {
            oacc[dn][0] *= f0; oacc[dn][1] *= f0;
            oacc[dn][2] *= f1; oacc[dn][3] *= f1;
        }

        // ---- O += P @ V ----
#pragma unroll
        for (int kk = 0; kk < 4; kk++) {
            unsigned ah_[4], al_[4];
            const int t0 = 2 * kk, t1 = 2 * kk + 1;
            split2pack(sacc[t0][0], sacc[t0][1], ah_[0], al_[0]);
            split2pack(sacc[t0][2], sacc[t0][3], ah_[1], al_[1]);
            split2pack(sacc[t1][0], sacc[t1][1], ah_[2], al_[2]);
            split2pack(sacc[t1][2], sacc[t1][3], ah_[3], al_[3]);
#pragma unroll
            for (int dp = 0; dp < 4; dp++) {
                const uint32_t offV =
                    2u * (unsigned)((dp * 16 + ld_row) * PADV + kk * 16 + ld_col);
                unsigned vh4[4], vl4[4];
                ldm_x4(vh4, uVh + offV);
                ldm_x4(vl4, uVl + offV);
                mma16816(oacc[2 * dp],     ah_, vh4);
                mma16816(oacc[2 * dp],     ah_, vl4);
                mma16816(oacc[2 * dp],     al_, vh4);
                mma16816(oacc[2 * dp + 1], ah_, vh4 + 2);
                mma16816(oacc[2 * dp + 1], ah_, vl4 + 2);
                mma16816(oacc[2 * dp + 1], al_, vh4 + 2);
            }
        }
        __syncthreads();
    }

    // ---- epilogue ----
    const float inv0 = 1.f / l0, inv1 = 1.f / l1;
    const int b = z >> 4, h = z & (HEADS - 1);
#pragma unroll
    for (int dn = 0; dn < 8; dn++) {
        const int c = h * DH + dn * 8 + tk;
        size_t i0 = ((size_t)(b * SEQ + r0)) * DMODEL + c;
        size_t i1 = ((size_t)(b * SEQ + r0 + 8)) * DMODEL + c;
        unsigned uh, ul;
        split2pack(oacc[dn][0] * inv0, oacc[dn][1] * inv0, uh, ul);
        *(unsigned*)(Oh + i0) = uh; *(unsigned*)(Ol + i0) = ul;
        split2pack(oacc[dn][2] * inv1, oacc[dn][3] * inv1, uh, ul);
        *(unsigned*)(Oh + i1) = uh; *(unsigned*)(Ol + i1) = ul;
    }
}

// ---------------------------------------------------------------------------
extern "C" void kernel_launch(void* const* d_in, const int* in_sizes, int n_in,
                              void* d_out, int out_size)
{
    const float* v  = (const float*)d_in[0];
    const float* k  = (const float*)d_in[1];
    const float* q  = (const float*)d_in[2];
    const float* wq = (const float*)d_in[3];
    const float* bq = (const float*)d_in[4];
    const float* wk = (const float*)d_in[5];
    const float* bk = (const float*)d_in[6];
    const float* wv = (const float*)d_in[7];
    const float* bv = (const float*)d_in[8];
    const float* wo = (const float*)d_in[9];
    const float* bo = (const float*)d_in[10];
    float* out = (float*)d_out;

    bf16 *q_hi, *q_lo, *k_hi, *k_lo, *v_hi, *v_lo;
    bf16 *wqT_hi, *wqT_lo, *wkT_hi, *wkT_lo, *wvT_hi, *wvT_lo, *woT_hi, *woT_lo;
    bf16 *Qh_hi, *Qh_lo, *Kh_hi, *Kh_lo, *VhT_hi, *VhT_lo, *Att_hi, *Att_lo;
    cudaGetSymbolAddress((void**)&q_hi,  g_q_hi);  cudaGetSymbolAddress((void**)&q_lo,  g_q_lo);
    cudaGetSymbolAddress((void**)&k_hi,  g_k_hi);  cudaGetSymbolAddress((void**)&k_lo,  g_k_lo);
    cudaGetSymbolAddress((void**)&v_hi,  g_v_hi);  cudaGetSymbolAddress((void**)&v_lo,  g_v_lo);
    cudaGetSymbolAddress((void**)&wqT_hi, g_wqT_hi); cudaGetSymbolAddress((void**)&wqT_lo, g_wqT_lo);
    cudaGetSymbolAddress((void**)&wkT_hi, g_wkT_hi); cudaGetSymbolAddress((void**)&wkT_lo, g_wkT_lo);
    cudaGetSymbolAddress((void**)&wvT_hi, g_wvT_hi); cudaGetSymbolAddress((void**)&wvT_lo, g_wvT_lo);
    cudaGetSymbolAddress((void**)&woT_hi, g_woT_hi); cudaGetSymbolAddress((void**)&woT_lo, g_woT_lo);
    cudaGetSymbolAddress((void**)&Qh_hi,  g_Qh_hi);  cudaGetSymbolAddress((void**)&Qh_lo,  g_Qh_lo);
    cudaGetSymbolAddress((void**)&Kh_hi,  g_Kh_hi);  cudaGetSymbolAddress((void**)&Kh_lo,  g_Kh_lo);
    cudaGetSymbolAddress((void**)&VhT_hi, g_VhT_hi); cudaGetSymbolAddress((void**)&VhT_lo, g_VhT_lo);
    cudaGetSymbolAddress((void**)&Att_hi, g_Att_hi); cudaGetSymbolAddress((void**)&Att_lo, g_Att_lo);

    const size_t smemGE = (size_t)(8 * 128 * 40) * sizeof(bf16);          // 81920
    const size_t smemFA = (size_t)(8 * 64 * 72) * sizeof(bf16);           // 73728
    cudaFuncSetAttribute(gemm3_qkv, cudaFuncAttributeMaxDynamicSharedMemorySize, (int)smemGE);
    cudaFuncSetAttribute(gemm3_out, cudaFuncAttributeMaxDynamicSharedMemorySize, (int)smemGE);
    cudaFuncSetAttribute(flash_attn, cudaFuncAttributeMaxDynamicSharedMemorySize, (int)smemFA);

    // launch 0: split q,k,v   launch 1: transpose+split weights
    {
        dim3 g(512, 3);
        split3_k<<<g, 256>>>(q, k, v, q_hi, q_lo, k_hi, k_lo, v_hi, v_lo);
    }
    {
        dim3 g(32, 32, 4), b(32, 8);
        tsplit4_k<<<g, b>>>(wq, wk, wv, wo,
                            wqT_hi, wqT_lo, wkT_hi, wkT_lo,
                            wvT_hi, wvT_lo, woT_hi, woT_lo);
    }

    // launch 2: all three QKV projections in one z-batched grid
    {
        dim3 grid(DMODEL / 128, NROWS / 128, 3);
        gemm3_qkv<<<grid, 256, smemGE>>>(q_hi, q_lo, k_hi, k_lo, v_hi, v_lo,
                                         wqT_hi, wqT_lo, wkT_hi, wkT_lo, wvT_hi, wvT_lo,
                                         bq, bk, bv,
                                         Qh_hi, Qh_lo, Kh_hi, Kh_lo, VhT_hi, VhT_lo);
    }

    // launch 3: fused attention (2 CTAs/SM)
    {
        dim3 grid(SEQ / 128, ZBH);
        flash_attn<<<grid, 256, smemFA>>>(Qh_hi, Qh_lo, Kh_hi, Kh_lo,
                                          VhT_hi, VhT_lo, Att_hi, Att_lo);
    }

    // launch 4: out = Att @ wo + bo (fp32 out)
    {
        dim3 grid(DMODEL / 128, NROWS / 128);
        gemm3_out<<<grid, 256, smemGE>>>(Att_hi, Att_lo, woT_hi, woT_lo, bo, out);
    }
}